// round 7
// baseline (speedup 1.0000x reference)
#include <cuda_runtime.h>
#include <cuda_fp16.h>
#include <cuda_bf16.h>
#include <cstdint>
#include <type_traits>

// ---------------------------------------------------------------------------
// CausalAttention (random-feature attention) — mma.sync 3-term split GEMMs,
// RN drain every 2 k-chunks (HMMA chains <= 12), zero-C chunk starts,
// 512-thread CTAs (16 warps, 16x64 warp tiles), 1 syncthreads per k-iter.
// ---------------------------------------------------------------------------

#define T_DIM 2048
#define B_DIM 8
#define E_DIM 1024
#define H_DIM 16
#define TB    (T_DIM * B_DIM)          // 16384 rows
#define EPS_RFA 1e-6f

#define BM 128
#define BN 128
#define BK 32
#define NKT (E_DIM / BK)                // 32
#define ROW_B 80
#define ARR_B (128 * ROW_B)
#define STAGE_B (4 * ARR_B)
#define NSTAGE 3
#define SM_BIAS 0
#define SM_STAGE0 1024
#define SM_TOTAL (SM_STAGE0 + NSTAGE * STAGE_B)   // 123904

// ------------------------- scratch (static device) -------------------------
__device__ __half g_x_hi[TB * E_DIM];
__device__ __half g_x_lo[TB * E_DIM];
__device__ __half g_Wq_hi[E_DIM * E_DIM];
__device__ __half g_Wq_lo[E_DIM * E_DIM];
__device__ __half g_Wk_hi[E_DIM * E_DIM];
__device__ __half g_Wk_lo[E_DIM * E_DIM];
__device__ __half g_Wv_hi[E_DIM * E_DIM];
__device__ __half g_Wv_lo[E_DIM * E_DIM];
__device__ __nv_bfloat16 g_Wo_hi[E_DIM * E_DIM];
__device__ __nv_bfloat16 g_Wo_lo[E_DIM * E_DIM];
__device__ float g_bq_eff[E_DIM];
__device__ float g_bk_eff[E_DIM];
__device__ float g_v   [TB * E_DIM];
__device__ float g_phiq[(size_t)TB * 2048];
__device__ float g_phik[(size_t)TB * 2048];
__device__ __nv_bfloat16 g_attn_hi[TB * E_DIM];
__device__ __nv_bfloat16 g_attn_lo[TB * E_DIM];

// ----------------------------- PTX helpers ---------------------------------
__device__ __forceinline__ uint32_t smem_to_u32(const void* p) {
    uint32_t a;
    asm("{ .reg .u64 t; cvta.to.shared.u64 t, %1; cvt.u32.u64 %0, t; }" : "=r"(a) : "l"(p));
    return a;
}
__device__ __forceinline__ void cp16(uint32_t dst, const void* src) {
    asm volatile("cp.async.cg.shared.global [%0], [%1], 16;" :: "r"(dst), "l"(src) : "memory");
}
#define CP_COMMIT() asm volatile("cp.async.commit_group;" ::: "memory")
#define CP_WAIT1()  asm volatile("cp.async.wait_group 1;" ::: "memory")

__device__ __forceinline__ void ldsm4(uint32_t* r, uint32_t addr) {
    asm volatile("ldmatrix.sync.aligned.m8n8.x4.shared.b16 {%0,%1,%2,%3}, [%4];"
                 : "=r"(r[0]), "=r"(r[1]), "=r"(r[2]), "=r"(r[3]) : "r"(addr));
}
// accumulate variants (d == c)
__device__ __forceinline__ void mma_f16(float* d, const uint32_t* a, const uint32_t* b) {
    asm volatile(
        "mma.sync.aligned.m16n8k16.row.col.f32.f16.f16.f32 "
        "{%0,%1,%2,%3}, {%4,%5,%6,%7}, {%8,%9}, {%0,%1,%2,%3};"
        : "+f"(d[0]), "+f"(d[1]), "+f"(d[2]), "+f"(d[3])
        : "r"(a[0]), "r"(a[1]), "r"(a[2]), "r"(a[3]), "r"(b[0]), "r"(b[1]));
}
__device__ __forceinline__ void mma_bf16(float* d, const uint32_t* a, const uint32_t* b) {
    asm volatile(
        "mma.sync.aligned.m16n8k16.row.col.f32.bf16.bf16.f32 "
        "{%0,%1,%2,%3}, {%4,%5,%6,%7}, {%8,%9}, {%0,%1,%2,%3};"
        : "+f"(d[0]), "+f"(d[1]), "+f"(d[2]), "+f"(d[3])
        : "r"(a[0]), "r"(a[1]), "r"(a[2]), "r"(a[3]), "r"(b[0]), "r"(b[1]));
}
// zero-C variants (d written fresh, c = 0) — start of each drain group
__device__ __forceinline__ void mma_f16_zc(float* d, const uint32_t* a, const uint32_t* b) {
    asm volatile(
        "mma.sync.aligned.m16n8k16.row.col.f32.f16.f16.f32 "
        "{%0,%1,%2,%3}, {%4,%5,%6,%7}, {%8,%9}, {%10,%10,%10,%10};"
        : "=f"(d[0]), "=f"(d[1]), "=f"(d[2]), "=f"(d[3])
        : "r"(a[0]), "r"(a[1]), "r"(a[2]), "r"(a[3]), "r"(b[0]), "r"(b[1]),
          "f"(0.0f));
}
__device__ __forceinline__ void mma_bf16_zc(float* d, const uint32_t* a, const uint32_t* b) {
    asm volatile(
        "mma.sync.aligned.m16n8k16.row.col.f32.bf16.bf16.f32 "
        "{%0,%1,%2,%3}, {%4,%5,%6,%7}, {%8,%9}, {%10,%10,%10,%10};"
        : "=f"(d[0]), "=f"(d[1]), "=f"(d[2]), "=f"(d[3])
        : "r"(a[0]), "r"(a[1]), "r"(a[2]), "r"(a[3]), "r"(b[0]), "r"(b[1]),
          "f"(0.0f));
}

// ---------------------------------------------------------------------------
// fp32 -> fp16 hi/lo split (with pre-scale)
// ---------------------------------------------------------------------------
__global__ void __launch_bounds__(256) f32_to_f16hl(
    const float* __restrict__ in, __half* __restrict__ hi,
    __half* __restrict__ lo, int n, float scale)
{
    int i = (blockIdx.x * 256 + threadIdx.x) * 4;
    if (i >= n) return;
    float4 v = *(const float4*)(in + i);
    float a[4] = {v.x * scale, v.y * scale, v.z * scale, v.w * scale};
    __half h[4], l[4];
#pragma unroll
    for (int j = 0; j < 4; j++) {
        h[j] = __float2half_rn(a[j]);
        l[j] = __float2half_rn(a[j] - __half2float(h[j]));
    }
    *(__half2*)(hi + i)     = __halves2half2(h[0], h[1]);
    *(__half2*)(hi + i + 2) = __halves2half2(h[2], h[3]);
    *(__half2*)(lo + i)     = __halves2half2(l[0], l[1]);
    *(__half2*)(lo + i + 2) = __halves2half2(l[2], l[3]);
}

// fp32 -> bf16 hi/lo split
__global__ void __launch_bounds__(256) f32_to_bf16hl(
    const float* __restrict__ in, __nv_bfloat16* __restrict__ hi,
    __nv_bfloat16* __restrict__ lo, int n)
{
    int i = (blockIdx.x * 256 + threadIdx.x) * 4;
    if (i >= n) return;
    float4 v = *(const float4*)(in + i);
    float a[4] = {v.x, v.y, v.z, v.w};
    __nv_bfloat16 h[4], l[4];
#pragma unroll
    for (int j = 0; j < 4; j++) {
        h[j] = __float2bfloat16(a[j]);
        l[j] = __float2bfloat16(a[j] - __bfloat162float(h[j]));
    }
    *(__nv_bfloat162*)(hi + i)     = __halves2bfloat162(h[0], h[1]);
    *(__nv_bfloat162*)(hi + i + 2) = __halves2bfloat162(h[2], h[3]);
    *(__nv_bfloat162*)(lo + i)     = __halves2bfloat162(l[0], l[1]);
    *(__nv_bfloat162*)(lo + i + 2) = __halves2bfloat162(l[2], l[3]);
}

// ---------------------------------------------------------------------------
// Weight prep: Weff[h*64+k, e] = scale * sum_d rm[h,k,d] * W[h*64+d, e]
// matrix written as fp16 hi/lo with extra x64; beff fp32 (logical scale).
// ---------------------------------------------------------------------------
__global__ void __launch_bounds__(256) prep_weff(
    const float* __restrict__ rm, const float* __restrict__ W,
    const float* __restrict__ bvec, __half* __restrict__ Whi,
    __half* __restrict__ Wlo, float* __restrict__ beff, float scale)
{
    const int h  = blockIdx.y;
    const int e0 = blockIdx.x * 64;
    const int tid = threadIdx.x;

    __shared__ float rs[64][65];
    __shared__ float ws[64][65];

    for (int i = tid; i < 4096; i += 256) {
        int k = i >> 6, dd = i & 63;
        rs[k][dd] = rm[h * 4096 + i];
    }
    for (int i = tid; i < 4096; i += 256) {
        int dd = i >> 6, e = i & 63;
        ws[dd][e] = W[(size_t)(h * 64 + dd) * E_DIM + e0 + e];
    }
    __syncthreads();

    const int tk = (tid >> 4) * 4;
    const int te = (tid & 15) * 4;
    float acc[4][4];
#pragma unroll
    for (int i = 0; i < 4; i++)
#pragma unroll
        for (int j = 0; j < 4; j++) acc[i][j] = 0.f;

#pragma unroll 8
    for (int dd = 0; dd < 64; dd++) {
        float a0 = rs[tk + 0][dd], a1 = rs[tk + 1][dd];
        float a2 = rs[tk + 2][dd], a3 = rs[tk + 3][dd];
        float b0 = ws[dd][te + 0], b1 = ws[dd][te + 1];
        float b2 = ws[dd][te + 2], b3 = ws[dd][te + 3];
        acc[0][0] += a0 * b0; acc[0][1] += a0 * b1; acc[0][2] += a0 * b2; acc[0][3] += a0 * b3;
        acc[1][0] += a1 * b0; acc[1][1] += a1 * b1; acc[1][2] += a1 * b2; acc[1][3] += a1 * b3;
        acc[2][0] += a2 * b0; acc[2][1] += a2 * b1; acc[2][2] += a2 * b2; acc[2][3] += a2 * b3;
        acc[3][0] += a3 * b0; acc[3][1] += a3 * b1; acc[3][2] += a3 * b2; acc[3][3] += a3 * b3;
    }
#pragma unroll
    for (int i = 0; i < 4; i++)
#pragma unroll
        for (int j = 0; j < 4; j++) {
            float val = 64.f * scale * acc[i][j];
            size_t idx = (size_t)(h * 64 + tk + i) * E_DIM + e0 + te + j;
            __half hv = __float2half_rn(val);
            Whi[idx] = hv;
            Wlo[idx] = __float2half_rn(val - __half2float(hv));
        }

    if (blockIdx.x == 0 && tid < 64) {
        float s = 0.f;
        for (int dd = 0; dd < 64; dd++) s += rs[tid][dd] * bvec[h * 64 + dd];
        beff[h * 64 + tid] = scale * s;
    }
}

// ---------------------------------------------------------------------------
// one k-stage loader — 512 threads: each thread does one 16B chunk per array
// ---------------------------------------------------------------------------
template <typename ET>
__device__ __forceinline__ void load_stage(
    const ET* __restrict__ Ahi, const ET* __restrict__ Alo,
    const ET* __restrict__ Bhi, const ET* __restrict__ Blo,
    int m0, int n0, int kc0, uint32_t st, int tid)
{
    const int row = tid >> 2;
    const int u = tid & 3;
    const uint32_t doff = row * ROW_B + u * 16;
    const size_t aoff = (size_t)(m0 + row) * E_DIM + kc0 + u * 8;
    const size_t boff = (size_t)(n0 + row) * E_DIM + kc0 + u * 8;
    cp16(st + doff,             Ahi + aoff);
    cp16(st + ARR_B + doff,     Alo + aoff);
    cp16(st + 2 * ARR_B + doff, Bhi + boff);
    cp16(st + 3 * ARR_B + doff, Blo + boff);
}

// ---------------------------------------------------------------------------
// HMMA GEMM: C = escale * (A @ B^T) + bias, 3-term split, drain every 2 chunks.
// 512 threads, 16 warps, warp tile 16x64.
// MODE 0: C fp32, row stride 1024.   MODE 1: phi epilogue, row stride 2048.
// ---------------------------------------------------------------------------
template <int MODE, typename ET>
__global__ void __launch_bounds__(512, 1) tc_gemm(
    const ET* __restrict__ Ahi, const ET* __restrict__ Alo,
    const ET* __restrict__ Bhi, const ET* __restrict__ Blo,
    const float* __restrict__ bias, float* __restrict__ Cout, float escale)
{
    extern __shared__ char smem[];
    const uint32_t sbase = smem_to_u32(smem);
    const int tid = threadIdx.x;
    const int wid = tid >> 5;
    const int lane = tid & 31;
    const int m0 = blockIdx.y * BM;
    const int n0 = blockIdx.x * BN;

    float* bias_s = (float*)(smem + SM_BIAS);
    if (tid < 128) bias_s[tid] = bias[n0 + tid];

    const int wm = wid >> 1;     // 0..7 -> rows wm*16
    const int wn = wid & 1;      // 0..1 -> cols wn*64
    const int g = lane >> 3;
    const int r = lane & 7;

    // preload 2 stages
    load_stage(Ahi, Alo, Bhi, Blo, m0, n0, 0,  sbase + SM_STAGE0, tid);
    CP_COMMIT();
    load_stage(Ahi, Alo, Bhi, Blo, m0, n0, BK, sbase + SM_STAGE0 + STAGE_B, tid);
    CP_COMMIT();

    float accm[8][4];
    float accw[8][4];
#pragma unroll
    for (int j = 0; j < 8; j++)
#pragma unroll
        for (int c = 0; c < 4; c++) accm[j][c] = 0.f;

    const uint32_t a_row_off = (uint32_t)((wm * 16 + (g & 1) * 8 + r) * ROW_B + (g >> 1) * 16);
    const uint32_t b_row_off = (uint32_t)((wn * 64 + (g >> 1) * 8 + r) * ROW_B + (g & 1) * 16);

#pragma unroll 1
    for (int kt = 0; kt < NKT; kt++) {
        CP_WAIT1();
        __syncthreads();    // slot kt%3 ready; prior iter reads of slot (kt-1)%3 done

        if (kt + 2 < NKT)
            load_stage(Ahi, Alo, Bhi, Blo, m0, n0, (kt + 2) * BK,
                       sbase + SM_STAGE0 + ((kt + 2) % NSTAGE) * STAGE_B, tid);
        CP_COMMIT();

        const uint32_t st = sbase + SM_STAGE0 + (kt % NSTAGE) * STAGE_B;
        const uint32_t sA[2] = { st, st + ARR_B };
        const uint32_t sB[2] = { st + 2 * ARR_B, st + 3 * ARR_B };
        const bool fresh = ((kt & 1) == 0);

#pragma unroll
        for (int ks = 0; ks < 2; ks++) {
            uint32_t afr[2][4];      // [hl][4]
            uint32_t bfr[4][2][4];   // [jp][hl][4]
#pragma unroll
            for (int hl = 0; hl < 2; hl++)
                ldsm4(afr[hl], sA[hl] + a_row_off + ks * 32);
#pragma unroll
            for (int jp = 0; jp < 4; jp++)
#pragma unroll
                for (int hl = 0; hl < 2; hl++)
                    ldsm4(bfr[jp][hl], sB[hl] + b_row_off + jp * (16 * ROW_B) + ks * 32);

#pragma unroll
            for (int t = 0; t < 3; t++) {
                const int pa = (t == 2) ? 1 : 0;   // hh, hl, lh
                const int pb = (t == 1) ? 1 : 0;
                const bool zc = fresh && ks == 0 && t == 0;
#pragma unroll
                for (int j = 0; j < 8; j++) {
                    const uint32_t* bj = &bfr[j >> 1][pb][(j & 1) * 2];
                    if (std::is_same<ET, __half>::value) {
                        if (zc) mma_f16_zc(accw[j], afr[pa], bj);
                        else    mma_f16(accw[j], afr[pa], bj);
                    } else {
                        if (zc) mma_bf16_zc(accw[j], afr[pa], bj);
                        else    mma_bf16(accw[j], afr[pa], bj);
                    }
                }
            }
        }
        if (kt & 1) {   // drain working -> master (IEEE-RN) every 2 chunks
#pragma unroll
            for (int j = 0; j < 8; j++)
#pragma unroll
                for (int c = 0; c < 4; c++) accm[j][c] += accw[j][c];
        }
    }

    // ------------------------------ epilogue --------------------------------
    const int qr = lane >> 2;
    const int qc = (lane & 3) * 2;
    const int row0 = m0 + wm * 16 + qr;
#pragma unroll
    for (int j = 0; j < 8; j++) {
        const int coll = wn * 64 + j * 8 + qc;
        const int col = n0 + coll;
        const float b0 = bias_s[coll], b1 = bias_s[coll + 1];
        if (MODE == 0) {
            float2 v0 = make_float2(accm[j][0] * escale + b0,
                                    accm[j][1] * escale + b1);
            float2 v1 = make_float2(accm[j][2] * escale + b0,
                                    accm[j][3] * escale + b1);
            *(float2*)(Cout + (size_t)row0 * E_DIM + col) = v0;
            *(float2*)(Cout + (size_t)(row0 + 8) * E_DIM + col) = v1;
        } else {
            const int h = col >> 6, k = col & 63;
            float s0, c0s, s1, c1s, s2, c2s, s3, c3s;
            __sincosf(accm[j][0] * escale + b0, &s0, &c0s);
            __sincosf(accm[j][1] * escale + b1, &s1, &c1s);
            __sincosf(accm[j][2] * escale + b0, &s2, &c2s);
            __sincosf(accm[j][3] * escale + b1, &s3, &c3s);
            float* p0 = Cout + (size_t)row0 * 2048 + h * 128 + k;
            float* p1 = Cout + (size_t)(row0 + 8) * 2048 + h * 128 + k;
            p0[0] = s0 * 0.125f; p0[1]  = s1 * 0.125f;
            p0[64] = c0s * 0.125f; p0[65] = c1s * 0.125f;
            p1[0] = s2 * 0.125f; p1[1]  = s3 * 0.125f;
            p1[64] = c2s * 0.125f; p1[65] = c3s * 0.125f;
        }
    }
}

// ---------------------------------------------------------------------------
// Causal RFA scan. One block per (b,h); 256 threads; ONE sync per timestep
// (double-buffered input tiles AND reduction buffers). attn -> bf16 hi/lo.
// ---------------------------------------------------------------------------
__global__ void __launch_bounds__(256) rfa_scan(
    const float* __restrict__ phiq, const float* __restrict__ phik,
    const float* __restrict__ v, __nv_bfloat16* __restrict__ attn_hi,
    __nv_bfloat16* __restrict__ attn_lo)
{
    const int bx = blockIdx.x;
    const int h = bx & 15;
    const int b = bx >> 4;
    const int tid = threadIdx.x;
    const int d = tid & 63;
    const int kg = tid >> 6;

    __shared__ float s_pq[2][128], s_pk[2][128], s_v[2][64];
    __shared__ float s_z[128];
    __shared__ float s_red[2][256];
    __shared__ float s_qzp[2][4];

    float s_loc[32];
#pragma unroll
    for (int j = 0; j < 32; j++) s_loc[j] = 0.f;
    if (tid < 128) s_z[tid] = 0.f;

    const size_t phi_stride = (size_t)B_DIM * 2048;
    const size_t v_stride   = (size_t)B_DIM * 1024;
    const float* pq_base = phiq + (size_t)b * 2048 + h * 128;
    const float* pk_base = phik + (size_t)b * 2048 + h * 128;
    const float* v_base  = v    + (size_t)b * 1024 + h * 64;
    const size_t o_off   = (size_t)b * 1024 + h * 64;

    float ld_pq = 0.f, ld_pk = 0.f, ld_v = 0.f;
    if (tid < 128) { ld_pq = pq_base[tid]; ld_pk = pk_base[tid]; }
    if (tid < 64)  { ld_v = v_base[tid]; }
    int buf = 0, rb = 0;
    if (tid < 128) { s_pq[0][tid] = ld_pq; s_pk[0][tid] = ld_pk; }
    if (tid < 64)  { s_v[0][tid] = ld_v; }
    __syncthreads();

    for (int t = 0; t < T_DIM; t++) {
        // prefetch t+1 (gmem -> regs; no smem touch yet)
        if (t + 1 < T_DIM) {
            if (tid < 128) {
                ld_pq = pq_base[(size_t)(t + 1) * phi_stride + tid];
                ld_pk = pk_base[(size_t)(t + 1) * phi_stride + tid];
            }
            if (tid < 64) ld_v = v_base[(size_t)(t + 1) * v_stride + tid];
        }

        // s update + q.s partials (reads buf)
        const float vd = s_v[buf][d];
        const float* pkp = &s_pk[buf][kg * 32];
        const float* pqp = &s_pq[buf][kg * 32];
        float acc0 = 0.f, acc1 = 0.f, acc2 = 0.f, acc3 = 0.f;
#pragma unroll
        for (int j = 0; j < 32; j += 4) {
            float4 pk4 = *(const float4*)(pkp + j);
            float4 pq4 = *(const float4*)(pqp + j);
            s_loc[j + 0] += pk4.x * vd; acc0 += pq4.x * s_loc[j + 0];
            s_loc[j + 1] += pk4.y * vd; acc1 += pq4.y * s_loc[j + 1];
            s_loc[j + 2] += pk4.z * vd; acc2 += pq4.z * s_loc[j + 2];
            s_loc[j + 3] += pk4.w * vd; acc3 += pq4.w * s_loc[j + 3];
        }
        s_red[rb][tid] = (acc0 + acc1) + (acc2 + acc3);

        // z update + qz partials
        float qzp = 0.f;
        if (tid < 128) {
            float zn = s_z[tid] + s_pk[buf][tid];
            s_z[tid] = zn;
            qzp = s_pq[buf][tid] * zn;
        }
#pragma unroll
        for (int off = 16; off; off >>= 1)
            qzp += __shfl_xor_sync(0xffffffffu, qzp, off);
        if (tid < 128 && (tid & 31) == 0) s_qzp[rb][tid >> 5] = qzp;

        // stage t+1 into the other buffer (pre-sync; prior readers of buf^1
        // finished before the PREVIOUS sync)
        if (t + 1 < T_DIM) {
            if (tid < 128) { s_pq[buf ^ 1][tid] = ld_pq; s_pk[buf ^ 1][tid] = ld_pk; }
            if (tid < 64)  { s_v[buf ^ 1][tid] = ld_v; }
        }

        __syncthreads();

        // finalize + write attn[t] (reads s_red[rb]; next iter writes rb^1)
        if (tid < 64) {
            float qs = (s_red[rb][d] + s_red[rb][64 + d]) +
                       (s_red[rb][128 + d] + s_red[rb][192 + d]);
            float qz = (s_qzp[rb][0] + s_qzp[rb][1]) + (s_qzp[rb][2] + s_qzp[rb][3]);
            qz = fmaxf(qz, EPS_RFA);
            float o = qs / qz;
            __nv_bfloat16 hv = __float2bfloat16(o);
            size_t idx = (size_t)t * v_stride + o_off + d;
            attn_hi[idx] = hv;
            attn_lo[idx] = __float2bfloat16(o - __bfloat162float(hv));
        }

        buf ^= 1;
        rb ^= 1;
    }
}

// ---------------------------------------------------------------------------
extern "C" void kernel_launch(void* const* d_in, const int* in_sizes, int n_in,
                              void* d_out, int out_size)
{
    const float* x  = (const float*)d_in[0];
    const float* rm = (const float*)d_in[1];
    const float* Wq = (const float*)d_in[2];
    const float* bq = (const float*)d_in[3];
    const float* Wk = (const float*)d_in[4];
    const float* bk = (const float*)d_in[5];
    const float* Wv = (const float*)d_in[6];
    const float* bv = (const float*)d_in[7];
    const float* Wo = (const float*)d_in[8];
    const float* bo = (const float*)d_in[9];
    float* out = (float*)d_out;

    __half *x_hi, *x_lo, *Wq_hi, *Wq_lo, *Wk_hi, *Wk_lo, *Wv_hi, *Wv_lo;
    __nv_bfloat16 *Wo_hi, *Wo_lo, *attn_hi, *attn_lo;
    float *bq_eff, *bk_eff, *vbuf, *phiq, *phik;
    cudaGetSymbolAddress((void**)&x_hi, g_x_hi);
    cudaGetSymbolAddress((void**)&x_lo, g_x_lo);
    cudaGetSymbolAddress((void**)&Wq_hi, g_Wq_hi);
    cudaGetSymbolAddress((void**)&Wq_lo, g_Wq_lo);
    cudaGetSymbolAddress((void**)&Wk_hi, g_Wk_hi);
    cudaGetSymbolAddress((void**)&Wk_lo, g_Wk_lo);
    cudaGetSymbolAddress((void**)&Wv_hi, g_Wv_hi);
    cudaGetSymbolAddress((void**)&Wv_lo, g_Wv_lo);
    cudaGetSymbolAddress((void**)&Wo_hi, g_Wo_hi);
    cudaGetSymbolAddress((void**)&Wo_lo, g_Wo_lo);
    cudaGetSymbolAddress((void**)&attn_hi, g_attn_hi);
    cudaGetSymbolAddress((void**)&attn_lo, g_attn_lo);
    cudaGetSymbolAddress((void**)&bq_eff, g_bq_eff);
    cudaGetSymbolAddress((void**)&bk_eff, g_bk_eff);
    cudaGetSymbolAddress((void**)&vbuf, g_v);
    cudaGetSymbolAddress((void**)&phiq, g_phiq);
    cudaGetSymbolAddress((void**)&phik, g_phik);

    cudaFuncSetAttribute((const void*)tc_gemm<0, __half>,
                         cudaFuncAttributeMaxDynamicSharedMemorySize, SM_TOTAL);
    cudaFuncSetAttribute((const void*)tc_gemm<1, __half>,
                         cudaFuncAttributeMaxDynamicSharedMemorySize, SM_TOTAL);
    cudaFuncSetAttribute((const void*)tc_gemm<0, __nv_bfloat16>,
                         cudaFuncAttributeMaxDynamicSharedMemorySize, SM_TOTAL);

    // conversions + weight prep: x scaled x256 (fp16 lo stays normal),
    // fp16 weights x64; bf16 Wo unscaled.
    f32_to_f16hl<<<TB * E_DIM / 1024, 256>>>(x, x_hi, x_lo, TB * E_DIM, 256.0f);
    prep_weff<<<dim3(16, 16), 256>>>(rm, Wq, bq, Wq_hi, Wq_lo, bq_eff, 0.125f);
    prep_weff<<<dim3(16, 16), 256>>>(rm, Wk, bk, Wk_hi, Wk_lo, bk_eff, 1.0f);
    f32_to_f16hl<<<E_DIM * E_DIM / 1024, 256>>>(Wv, Wv_hi, Wv_lo, E_DIM * E_DIM, 64.0f);
    f32_to_bf16hl<<<E_DIM * E_DIM / 1024, 256>>>(Wo, Wo_hi, Wo_lo, E_DIM * E_DIM);

    // tensor-core GEMMs (escale undoes x256 * x64)
    dim3 gg(E_DIM / BN, TB / BM);   // (8, 128)
    const float inv = 1.0f / 16384.0f;
    tc_gemm<1, __half><<<gg, 512, SM_TOTAL>>>(x_hi, x_lo, Wq_hi, Wq_lo, bq_eff, phiq, inv);
    tc_gemm<1, __half><<<gg, 512, SM_TOTAL>>>(x_hi, x_lo, Wk_hi, Wk_lo, bk_eff, phik, inv);
    tc_gemm<0, __half><<<gg, 512, SM_TOTAL>>>(x_hi, x_lo, Wv_hi, Wv_lo, bv, vbuf, inv);

    // causal scan (writes attn bf16 split)
    rfa_scan<<<B_DIM * H_DIM, 256>>>(phiq, phik, vbuf, attn_hi, attn_lo);

    // output projection (bf16 split, unamplified error path)
    tc_gemm<0, __nv_bfloat16><<<gg, 512, SM_TOTAL>>>(attn_hi, attn_lo, Wo_hi, Wo_lo, bo, out, 1.0f);
}

// round 8
// speedup vs baseline: 1.0040x; 1.0040x over previous
#include <cuda_runtime.h>
#include <cuda_fp16.h>
#include <cuda_bf16.h>
#include <cstdint>
#include <type_traits>

// ---------------------------------------------------------------------------
// CausalAttention (random-feature attention) — mma.sync 3-term split GEMMs.
// R6 tile config (256 thr, 32x64 warp tiles) + zero-C chunk starts +
// drain every chunk (HMMA chains <= 6) + single-sync pipeline + 1-sync scan.
// ---------------------------------------------------------------------------

#define T_DIM 2048
#define B_DIM 8
#define E_DIM 1024
#define H_DIM 16
#define TB    (T_DIM * B_DIM)          // 16384 rows
#define EPS_RFA 1e-6f

#define BM 128
#define BN 128
#define BK 32
#define NKT (E_DIM / BK)                // 32
#define ROW_B 80
#define ARR_B (128 * ROW_B)
#define STAGE_B (4 * ARR_B)
#define NSTAGE 3
#define SM_BIAS 0
#define SM_STAGE0 1024
#define SM_TOTAL (SM_STAGE0 + NSTAGE * STAGE_B)   // 123904

// ------------------------- scratch (static device) -------------------------
__device__ __half g_x_hi[TB * E_DIM];
__device__ __half g_x_lo[TB * E_DIM];
__device__ __half g_Wq_hi[E_DIM * E_DIM];
__device__ __half g_Wq_lo[E_DIM * E_DIM];
__device__ __half g_Wk_hi[E_DIM * E_DIM];
__device__ __half g_Wk_lo[E_DIM * E_DIM];
__device__ __half g_Wv_hi[E_DIM * E_DIM];
__device__ __half g_Wv_lo[E_DIM * E_DIM];
__device__ __nv_bfloat16 g_Wo_hi[E_DIM * E_DIM];
__device__ __nv_bfloat16 g_Wo_lo[E_DIM * E_DIM];
__device__ float g_bq_eff[E_DIM];
__device__ float g_bk_eff[E_DIM];
__device__ float g_v   [TB * E_DIM];
__device__ float g_phiq[(size_t)TB * 2048];
__device__ float g_phik[(size_t)TB * 2048];
__device__ __nv_bfloat16 g_attn_hi[TB * E_DIM];
__device__ __nv_bfloat16 g_attn_lo[TB * E_DIM];

// ----------------------------- PTX helpers ---------------------------------
__device__ __forceinline__ uint32_t smem_to_u32(const void* p) {
    uint32_t a;
    asm("{ .reg .u64 t; cvta.to.shared.u64 t, %1; cvt.u32.u64 %0, t; }" : "=r"(a) : "l"(p));
    return a;
}
__device__ __forceinline__ void cp16(uint32_t dst, const void* src) {
    asm volatile("cp.async.cg.shared.global [%0], [%1], 16;" :: "r"(dst), "l"(src) : "memory");
}
#define CP_COMMIT() asm volatile("cp.async.commit_group;" ::: "memory")
#define CP_WAIT1()  asm volatile("cp.async.wait_group 1;" ::: "memory")

__device__ __forceinline__ void ldsm4(uint32_t* r, uint32_t addr) {
    asm volatile("ldmatrix.sync.aligned.m8n8.x4.shared.b16 {%0,%1,%2,%3}, [%4];"
                 : "=r"(r[0]), "=r"(r[1]), "=r"(r[2]), "=r"(r[3]) : "r"(addr));
}
// accumulate variants (d == c)
__device__ __forceinline__ void mma_f16(float* d, const uint32_t* a, const uint32_t* b) {
    asm volatile(
        "mma.sync.aligned.m16n8k16.row.col.f32.f16.f16.f32 "
        "{%0,%1,%2,%3}, {%4,%5,%6,%7}, {%8,%9}, {%0,%1,%2,%3};"
        : "+f"(d[0]), "+f"(d[1]), "+f"(d[2]), "+f"(d[3])
        : "r"(a[0]), "r"(a[1]), "r"(a[2]), "r"(a[3]), "r"(b[0]), "r"(b[1]));
}
__device__ __forceinline__ void mma_bf16(float* d, const uint32_t* a, const uint32_t* b) {
    asm volatile(
        "mma.sync.aligned.m16n8k16.row.col.f32.bf16.bf16.f32 "
        "{%0,%1,%2,%3}, {%4,%5,%6,%7}, {%8,%9}, {%0,%1,%2,%3};"
        : "+f"(d[0]), "+f"(d[1]), "+f"(d[2]), "+f"(d[3])
        : "r"(a[0]), "r"(a[1]), "r"(a[2]), "r"(a[3]), "r"(b[0]), "r"(b[1]));
}
// zero-C variants (d written fresh, c = 0) — first MMA of each k-chunk
__device__ __forceinline__ void mma_f16_zc(float* d, const uint32_t* a, const uint32_t* b) {
    asm volatile(
        "mma.sync.aligned.m16n8k16.row.col.f32.f16.f16.f32 "
        "{%0,%1,%2,%3}, {%4,%5,%6,%7}, {%8,%9}, {%10,%10,%10,%10};"
        : "=f"(d[0]), "=f"(d[1]), "=f"(d[2]), "=f"(d[3])
        : "r"(a[0]), "r"(a[1]), "r"(a[2]), "r"(a[3]), "r"(b[0]), "r"(b[1]),
          "f"(0.0f));
}
__device__ __forceinline__ void mma_bf16_zc(float* d, const uint32_t* a, const uint32_t* b) {
    asm volatile(
        "mma.sync.aligned.m16n8k16.row.col.f32.bf16.bf16.f32 "
        "{%0,%1,%2,%3}, {%4,%5,%6,%7}, {%8,%9}, {%10,%10,%10,%10};"
        : "=f"(d[0]), "=f"(d[1]), "=f"(d[2]), "=f"(d[3])
        : "r"(a[0]), "r"(a[1]), "r"(a[2]), "r"(a[3]), "r"(b[0]), "r"(b[1]),
          "f"(0.0f));
}

// ---------------------------------------------------------------------------
// fp32 -> fp16 hi/lo split (with pre-scale)
// ---------------------------------------------------------------------------
__global__ void __launch_bounds__(256) f32_to_f16hl(
    const float* __restrict__ in, __half* __restrict__ hi,
    __half* __restrict__ lo, int n, float scale)
{
    int i = (blockIdx.x * 256 + threadIdx.x) * 4;
    if (i >= n) return;
    float4 v = *(const float4*)(in + i);
    float a[4] = {v.x * scale, v.y * scale, v.z * scale, v.w * scale};
    __half h[4], l[4];
#pragma unroll
    for (int j = 0; j < 4; j++) {
        h[j] = __float2half_rn(a[j]);
        l[j] = __float2half_rn(a[j] - __half2float(h[j]));
    }
    *(__half2*)(hi + i)     = __halves2half2(h[0], h[1]);
    *(__half2*)(hi + i + 2) = __halves2half2(h[2], h[3]);
    *(__half2*)(lo + i)     = __halves2half2(l[0], l[1]);
    *(__half2*)(lo + i + 2) = __halves2half2(l[2], l[3]);
}

// fp32 -> bf16 hi/lo split
__global__ void __launch_bounds__(256) f32_to_bf16hl(
    const float* __restrict__ in, __nv_bfloat16* __restrict__ hi,
    __nv_bfloat16* __restrict__ lo, int n)
{
    int i = (blockIdx.x * 256 + threadIdx.x) * 4;
    if (i >= n) return;
    float4 v = *(const float4*)(in + i);
    float a[4] = {v.x, v.y, v.z, v.w};
    __nv_bfloat16 h[4], l[4];
#pragma unroll
    for (int j = 0; j < 4; j++) {
        h[j] = __float2bfloat16(a[j]);
        l[j] = __float2bfloat16(a[j] - __bfloat162float(h[j]));
    }
    *(__nv_bfloat162*)(hi + i)     = __halves2bfloat162(h[0], h[1]);
    *(__nv_bfloat162*)(hi + i + 2) = __halves2bfloat162(h[2], h[3]);
    *(__nv_bfloat162*)(lo + i)     = __halves2bfloat162(l[0], l[1]);
    *(__nv_bfloat162*)(lo + i + 2) = __halves2bfloat162(l[2], l[3]);
}

// ---------------------------------------------------------------------------
// Weight prep: Weff[h*64+k, e] = scale * sum_d rm[h,k,d] * W[h*64+d, e]
// matrix written as fp16 hi/lo with extra x64; beff fp32 (logical scale).
// ---------------------------------------------------------------------------
__global__ void __launch_bounds__(256) prep_weff(
    const float* __restrict__ rm, const float* __restrict__ W,
    const float* __restrict__ bvec, __half* __restrict__ Whi,
    __half* __restrict__ Wlo, float* __restrict__ beff, float scale)
{
    const int h  = blockIdx.y;
    const int e0 = blockIdx.x * 64;
    const int tid = threadIdx.x;

    __shared__ float rs[64][65];
    __shared__ float ws[64][65];

    for (int i = tid; i < 4096; i += 256) {
        int k = i >> 6, dd = i & 63;
        rs[k][dd] = rm[h * 4096 + i];
    }
    for (int i = tid; i < 4096; i += 256) {
        int dd = i >> 6, e = i & 63;
        ws[dd][e] = W[(size_t)(h * 64 + dd) * E_DIM + e0 + e];
    }
    __syncthreads();

    const int tk = (tid >> 4) * 4;
    const int te = (tid & 15) * 4;
    float acc[4][4];
#pragma unroll
    for (int i = 0; i < 4; i++)
#pragma unroll
        for (int j = 0; j < 4; j++) acc[i][j] = 0.f;

#pragma unroll 8
    for (int dd = 0; dd < 64; dd++) {
        float a0 = rs[tk + 0][dd], a1 = rs[tk + 1][dd];
        float a2 = rs[tk + 2][dd], a3 = rs[tk + 3][dd];
        float b0 = ws[dd][te + 0], b1 = ws[dd][te + 1];
        float b2 = ws[dd][te + 2], b3 = ws[dd][te + 3];
        acc[0][0] += a0 * b0; acc[0][1] += a0 * b1; acc[0][2] += a0 * b2; acc[0][3] += a0 * b3;
        acc[1][0] += a1 * b0; acc[1][1] += a1 * b1; acc[1][2] += a1 * b2; acc[1][3] += a1 * b3;
        acc[2][0] += a2 * b0; acc[2][1] += a2 * b1; acc[2][2] += a2 * b2; acc[2][3] += a2 * b3;
        acc[3][0] += a3 * b0; acc[3][1] += a3 * b1; acc[3][2] += a3 * b2; acc[3][3] += a3 * b3;
    }
#pragma unroll
    for (int i = 0; i < 4; i++)
#pragma unroll
        for (int j = 0; j < 4; j++) {
            float val = 64.f * scale * acc[i][j];
            size_t idx = (size_t)(h * 64 + tk + i) * E_DIM + e0 + te + j;
            __half hv = __float2half_rn(val);
            Whi[idx] = hv;
            Wlo[idx] = __float2half_rn(val - __half2float(hv));
        }

    if (blockIdx.x == 0 && tid < 64) {
        float s = 0.f;
        for (int dd = 0; dd < 64; dd++) s += rs[tid][dd] * bvec[h * 64 + dd];
        beff[h * 64 + tid] = scale * s;
    }
}

// ---------------------------------------------------------------------------
// one k-stage loader — 256 threads, 2 iterations (8 cp.async per thread)
// ---------------------------------------------------------------------------
template <typename ET>
__device__ __forceinline__ void load_stage(
    const ET* __restrict__ Ahi, const ET* __restrict__ Alo,
    const ET* __restrict__ Bhi, const ET* __restrict__ Blo,
    int m0, int n0, int kc0, uint32_t st, int tid)
{
#pragma unroll
    for (int i = 0; i < 2; i++) {
        const int idx = tid + 256 * i;
        const int row = idx >> 2;
        const int u = idx & 3;
        const uint32_t doff = row * ROW_B + u * 16;
        const size_t aoff = (size_t)(m0 + row) * E_DIM + kc0 + u * 8;
        const size_t boff = (size_t)(n0 + row) * E_DIM + kc0 + u * 8;
        cp16(st + doff,             Ahi + aoff);
        cp16(st + ARR_B + doff,     Alo + aoff);
        cp16(st + 2 * ARR_B + doff, Bhi + boff);
        cp16(st + 3 * ARR_B + doff, Blo + boff);
    }
}

// ---------------------------------------------------------------------------
// HMMA GEMM: C = escale * (A @ B^T) + bias, 3-term split.
// 256 threads, 8 warps, warp tile 32x64; zero-C chunk starts; drain per chunk.
// MODE 0: C fp32, row stride 1024.   MODE 1: phi epilogue, row stride 2048.
// ---------------------------------------------------------------------------
template <int MODE, typename ET>
__global__ void __launch_bounds__(256, 1) tc_gemm(
    const ET* __restrict__ Ahi, const ET* __restrict__ Alo,
    const ET* __restrict__ Bhi, const ET* __restrict__ Blo,
    const float* __restrict__ bias, float* __restrict__ Cout, float escale)
{
    extern __shared__ char smem[];
    const uint32_t sbase = smem_to_u32(smem);
    const int tid = threadIdx.x;
    const int wid = tid >> 5;
    const int lane = tid & 31;
    const int m0 = blockIdx.y * BM;
    const int n0 = blockIdx.x * BN;

    float* bias_s = (float*)(smem + SM_BIAS);
    if (tid < 128) bias_s[tid] = bias[n0 + tid];

    const int wm = wid >> 1;     // 0..3 -> rows wm*32
    const int wn = wid & 1;      // 0..1 -> cols wn*64
    const int g = lane >> 3;
    const int r = lane & 7;

    // preload 2 stages (3 buffers total)
    load_stage(Ahi, Alo, Bhi, Blo, m0, n0, 0,  sbase + SM_STAGE0, tid);
    CP_COMMIT();
    load_stage(Ahi, Alo, Bhi, Blo, m0, n0, BK, sbase + SM_STAGE0 + STAGE_B, tid);
    CP_COMMIT();

    float accm[2][8][4];
    float accw[2][8][4];
#pragma unroll
    for (int mt = 0; mt < 2; mt++)
#pragma unroll
        for (int j = 0; j < 8; j++)
#pragma unroll
            for (int c = 0; c < 4; c++) accm[mt][j][c] = 0.f;

    const uint32_t a_row_off = (uint32_t)((wm * 32 + (g & 1) * 8 + r) * ROW_B + (g >> 1) * 16);
    const uint32_t b_row_off = (uint32_t)((wn * 64 + (g >> 1) * 8 + r) * ROW_B + (g & 1) * 16);

#pragma unroll 1
    for (int kt = 0; kt < NKT; kt++) {
        CP_WAIT1();
        __syncthreads();   // slot kt%3 ready; everyone done reading slot (kt-1)%3

        // refill slot (kt+2)%3 == (kt-1)%3 — safe after the sync above
        if (kt + 2 < NKT)
            load_stage(Ahi, Alo, Bhi, Blo, m0, n0, (kt + 2) * BK,
                       sbase + SM_STAGE0 + ((kt + 2) % NSTAGE) * STAGE_B, tid);
        CP_COMMIT();

        const uint32_t st = sbase + SM_STAGE0 + (kt % NSTAGE) * STAGE_B;
        const uint32_t sA[2] = { st, st + ARR_B };
        const uint32_t sB[2] = { st + 2 * ARR_B, st + 3 * ARR_B };

#pragma unroll
        for (int ks = 0; ks < 2; ks++) {
            uint32_t afr[2][2][4];   // [mt][hl][4]
            uint32_t bfr[4][2][4];   // [jp][hl][4]
#pragma unroll
            for (int mt = 0; mt < 2; mt++)
#pragma unroll
                for (int hl = 0; hl < 2; hl++)
                    ldsm4(afr[mt][hl], sA[hl] + a_row_off + mt * (16 * ROW_B) + ks * 32);
#pragma unroll
            for (int jp = 0; jp < 4; jp++)
#pragma unroll
                for (int hl = 0; hl < 2; hl++)
                    ldsm4(bfr[jp][hl], sB[hl] + b_row_off + jp * (16 * ROW_B) + ks * 32);

#pragma unroll
            for (int t = 0; t < 3; t++) {
                const int pa = (t == 2) ? 1 : 0;   // hh, hl, lh
                const int pb = (t == 1) ? 1 : 0;
                const bool zc = (ks == 0 && t == 0);   // first write per chunk
#pragma unroll
                for (int mt = 0; mt < 2; mt++)
#pragma unroll
                    for (int j = 0; j < 8; j++) {
                        const uint32_t* bj = &bfr[j >> 1][pb][(j & 1) * 2];
                        if (std::is_same<ET, __half>::value) {
                            if (zc) mma_f16_zc(accw[mt][j], afr[mt][pa], bj);
                            else    mma_f16(accw[mt][j], afr[mt][pa], bj);
                        } else {
                            if (zc) mma_bf16_zc(accw[mt][j], afr[mt][pa], bj);
                            else    mma_bf16(accw[mt][j], afr[mt][pa], bj);
                        }
                    }
            }
        }
        // drain working -> master (IEEE-RN), every chunk (chain length 6)
#pragma unroll
        for (int mt = 0; mt < 2; mt++)
#pragma unroll
            for (int j = 0; j < 8; j++)
#pragma unroll
                for (int c = 0; c < 4; c++) accm[mt][j][c] += accw[mt][j][c];
    }

    // ------------------------------ epilogue --------------------------------
    const int qr = lane >> 2;
    const int qc = (lane & 3) * 2;
#pragma unroll
    for (int mt = 0; mt < 2; mt++) {
        const int row0 = m0 + wm * 32 + mt * 16 + qr;
#pragma unroll
        for (int j = 0; j < 8; j++) {
            const int coll = wn * 64 + j * 8 + qc;
            const int col = n0 + coll;
            const float b0 = bias_s[coll], b1 = bias_s[coll + 1];
            if (MODE == 0) {
                float2 v0 = make_float2(accm[mt][j][0] * escale + b0,
                                        accm[mt][j][1] * escale + b1);
                float2 v1 = make_float2(accm[mt][j][2] * escale + b0,
                                        accm[mt][j][3] * escale + b1);
                *(float2*)(Cout + (size_t)row0 * E_DIM + col) = v0;
                *(float2*)(Cout + (size_t)(row0 + 8) * E_DIM + col) = v1;
            } else {
                const int h = col >> 6, k = col & 63;
                float s0, c0s, s1, c1s, s2, c2s, s3, c3s;
                __sincosf(accm[mt][j][0] * escale + b0, &s0, &c0s);
                __sincosf(accm[mt][j][1] * escale + b1, &s1, &c1s);
                __sincosf(accm[mt][j][2] * escale + b0, &s2, &c2s);
                __sincosf(accm[mt][j][3] * escale + b1, &s3, &c3s);
                float* p0 = Cout + (size_t)row0 * 2048 + h * 128 + k;
                float* p1 = Cout + (size_t)(row0 + 8) * 2048 + h * 128 + k;
                p0[0] = s0 * 0.125f; p0[1]  = s1 * 0.125f;
                p0[64] = c0s * 0.125f; p0[65] = c1s * 0.125f;
                p1[0] = s2 * 0.125f; p1[1]  = s3 * 0.125f;
                p1[64] = c2s * 0.125f; p1[65] = c3s * 0.125f;
            }
        }
    }
}

// ---------------------------------------------------------------------------
// Causal RFA scan. One block per (b,h); 256 threads; ONE sync per timestep.
// attn -> bf16 hi/lo.
// ---------------------------------------------------------------------------
__global__ void __launch_bounds__(256) rfa_scan(
    const float* __restrict__ phiq, const float* __restrict__ phik,
    const float* __restrict__ v, __nv_bfloat16* __restrict__ attn_hi,
    __nv_bfloat16* __restrict__ attn_lo)
{
    const int bx = blockIdx.x;
    const int h = bx & 15;
    const int b = bx >> 4;
    const int tid = threadIdx.x;
    const int d = tid & 63;
    const int kg = tid >> 6;

    __shared__ float s_pq[2][128], s_pk[2][128], s_v[2][64];
    __shared__ float s_z[128];
    __shared__ float s_red[2][256];
    __shared__ float s_qzp[2][4];

    float s_loc[32];
#pragma unroll
    for (int j = 0; j < 32; j++) s_loc[j] = 0.f;
    if (tid < 128) s_z[tid] = 0.f;

    const size_t phi_stride = (size_t)B_DIM * 2048;
    const size_t v_stride   = (size_t)B_DIM * 1024;
    const float* pq_base = phiq + (size_t)b * 2048 + h * 128;
    const float* pk_base = phik + (size_t)b * 2048 + h * 128;
    const float* v_base  = v    + (size_t)b * 1024 + h * 64;
    const size_t o_off   = (size_t)b * 1024 + h * 64;

    float ld_pq = 0.f, ld_pk = 0.f, ld_v = 0.f;
    if (tid < 128) { ld_pq = pq_base[tid]; ld_pk = pk_base[tid]; }
    if (tid < 64)  { ld_v = v_base[tid]; }
    int buf = 0, rb = 0;
    if (tid < 128) { s_pq[0][tid] = ld_pq; s_pk[0][tid] = ld_pk; }
    if (tid < 64)  { s_v[0][tid] = ld_v; }
    __syncthreads();

    for (int t = 0; t < T_DIM; t++) {
        if (t + 1 < T_DIM) {
            if (tid < 128) {
                ld_pq = pq_base[(size_t)(t + 1) * phi_stride + tid];
                ld_pk = pk_base[(size_t)(t + 1) * phi_stride + tid];
            }
            if (tid < 64) ld_v = v_base[(size_t)(t + 1) * v_stride + tid];
        }

        const float vd = s_v[buf][d];
        const float* pkp = &s_pk[buf][kg * 32];
        const float* pqp = &s_pq[buf][kg * 32];
        float acc0 = 0.f, acc1 = 0.f, acc2 = 0.f, acc3 = 0.f;
#pragma unroll
        for (int j = 0; j < 32; j += 4) {
            float4 pk4 = *(const float4*)(pkp + j);
            float4 pq4 = *(const float4*)(pqp + j);
            s_loc[j + 0] += pk4.x * vd; acc0 += pq4.x * s_loc[j + 0];
            s_loc[j + 1] += pk4.y * vd; acc1 += pq4.y * s_loc[j + 1];
            s_loc[j + 2] += pk4.z * vd; acc2 += pq4.z * s_loc[j + 2];
            s_loc[j + 3] += pk4.w * vd; acc3 += pq4.w * s_loc[j + 3];
        }
        s_red[rb][tid] = (acc0 + acc1) + (acc2 + acc3);

        float qzp = 0.f;
        if (tid < 128) {
            float zn = s_z[tid] + s_pk[buf][tid];
            s_z[tid] = zn;
            qzp = s_pq[buf][tid] * zn;
        }
#pragma unroll
        for (int off = 16; off; off >>= 1)
            qzp += __shfl_xor_sync(0xffffffffu, qzp, off);
        if (tid < 128 && (tid & 31) == 0) s_qzp[rb][tid >> 5] = qzp;

        if (t + 1 < T_DIM) {
            if (tid < 128) { s_pq[buf ^ 1][tid] = ld_pq; s_pk[buf ^ 1][tid] = ld_pk; }
            if (tid < 64)  { s_v[buf ^ 1][tid] = ld_v; }
        }

        __syncthreads();

        if (tid < 64) {
            float qs = (s_red[rb][d] + s_red[rb][64 + d]) +
                       (s_red[rb][128 + d] + s_red[rb][192 + d]);
            float qz = (s_qzp[rb][0] + s_qzp[rb][1]) + (s_qzp[rb][2] + s_qzp[rb][3]);
            qz = fmaxf(qz, EPS_RFA);
            float o = qs / qz;
            __nv_bfloat16 hv = __float2bfloat16(o);
            size_t idx = (size_t)t * v_stride + o_off + d;
            attn_hi[idx] = hv;
            attn_lo[idx] = __float2bfloat16(o - __bfloat162float(hv));
        }

        buf ^= 1;
        rb ^= 1;
    }
}

// ---------------------------------------------------------------------------
extern "C" void kernel_launch(void* const* d_in, const int* in_sizes, int n_in,
                              void* d_out, int out_size)
{
    const float* x  = (const float*)d_in[0];
    const float* rm = (const float*)d_in[1];
    const float* Wq = (const float*)d_in[2];
    const float* bq = (const float*)d_in[3];
    const float* Wk = (const float*)d_in[4];
    const float* bk = (const float*)d_in[5];
    const float* Wv = (const float*)d_in[6];
    const float* bv = (const float*)d_in[7];
    const float* Wo = (const float*)d_in[8];
    const float* bo = (const float*)d_in[9];
    float* out = (float*)d_out;

    __half *x_hi, *x_lo, *Wq_hi, *Wq_lo, *Wk_hi, *Wk_lo, *Wv_hi, *Wv_lo;
    __nv_bfloat16 *Wo_hi, *Wo_lo, *attn_hi, *attn_lo;
    float *bq_eff, *bk_eff, *vbuf, *phiq, *phik;
    cudaGetSymbolAddress((void**)&x_hi, g_x_hi);
    cudaGetSymbolAddress((void**)&x_lo, g_x_lo);
    cudaGetSymbolAddress((void**)&Wq_hi, g_Wq_hi);
    cudaGetSymbolAddress((void**)&Wq_lo, g_Wq_lo);
    cudaGetSymbolAddress((void**)&Wk_hi, g_Wk_hi);
    cudaGetSymbolAddress((void**)&Wk_lo, g_Wk_lo);
    cudaGetSymbolAddress((void**)&Wv_hi, g_Wv_hi);
    cudaGetSymbolAddress((void**)&Wv_lo, g_Wv_lo);
    cudaGetSymbolAddress((void**)&Wo_hi, g_Wo_hi);
    cudaGetSymbolAddress((void**)&Wo_lo, g_Wo_lo);
    cudaGetSymbolAddress((void**)&attn_hi, g_attn_hi);
    cudaGetSymbolAddress((void**)&attn_lo, g_attn_lo);
    cudaGetSymbolAddress((void**)&bq_eff, g_bq_eff);
    cudaGetSymbolAddress((void**)&bk_eff, g_bk_eff);
    cudaGetSymbolAddress((void**)&vbuf, g_v);
    cudaGetSymbolAddress((void**)&phiq, g_phiq);
    cudaGetSymbolAddress((void**)&phik, g_phik);

    cudaFuncSetAttribute((const void*)tc_gemm<0, __half>,
                         cudaFuncAttributeMaxDynamicSharedMemorySize, SM_TOTAL);
    cudaFuncSetAttribute((const void*)tc_gemm<1, __half>,
                         cudaFuncAttributeMaxDynamicSharedMemorySize, SM_TOTAL);
    cudaFuncSetAttribute((const void*)tc_gemm<0, __nv_bfloat16>,
                         cudaFuncAttributeMaxDynamicSharedMemorySize, SM_TOTAL);

    // conversions + weight prep: x scaled x256 (fp16 lo stays normal),
    // fp16 weights x64; bf16 Wo unscaled.
    f32_to_f16hl<<<TB * E_DIM / 1024, 256>>>(x, x_hi, x_lo, TB * E_DIM, 256.0f);
    prep_weff<<<dim3(16, 16), 256>>>(rm, Wq, bq, Wq_hi, Wq_lo, bq_eff, 0.125f);
    prep_weff<<<dim3(16, 16), 256>>>(rm, Wk, bk, Wk_hi, Wk_lo, bk_eff, 1.0f);
    f32_to_f16hl<<<E_DIM * E_DIM / 1024, 256>>>(Wv, Wv_hi, Wv_lo, E_DIM * E_DIM, 64.0f);
    f32_to_bf16hl<<<E_DIM * E_DIM / 1024, 256>>>(Wo, Wo_hi, Wo_lo, E_DIM * E_DIM);

    // tensor-core GEMMs (escale undoes x256 * x64)
    dim3 gg(E_DIM / BN, TB / BM);   // (8, 128)
    const float inv = 1.0f / 16384.0f;
    tc_gemm<1, __half><<<gg, 256, SM_TOTAL>>>(x_hi, x_lo, Wq_hi, Wq_lo, bq_eff, phiq, inv);
    tc_gemm<1, __half><<<gg, 256, SM_TOTAL>>>(x_hi, x_lo, Wk_hi, Wk_lo, bk_eff, phik, inv);
    tc_gemm<0, __half><<<gg, 256, SM_TOTAL>>>(x_hi, x_lo, Wv_hi, Wv_lo, bv, vbuf, inv);

    // causal scan (writes attn bf16 split)
    rfa_scan<<<B_DIM * H_DIM, 256>>>(phiq, phik, vbuf, attn_hi, attn_lo);

    // output projection (bf16 split, unamplified error path)
    tc_gemm<0, __nv_bfloat16><<<gg, 256, SM_TOTAL>>>(attn_hi, attn_lo, Wo_hi, Wo_lo, bo, out, 1.0f);
}

// round 9
// speedup vs baseline: 1.0086x; 1.0046x over previous
#include <cuda_runtime.h>
#include <cuda_fp16.h>
#include <cuda_bf16.h>
#include <cstdint>
#include <type_traits>

// ---------------------------------------------------------------------------
// CausalAttention (random-feature attention) — mma.sync 3-term split GEMMs.
// 256 thr, 32x64 warp tiles, zero-C chunk starts, per-chunk RN drain,
// 4-stage cp.async ring (prefetch distance 3), single sync per k-iter,
// 1-sync scan.
// ---------------------------------------------------------------------------

#define T_DIM 2048
#define B_DIM 8
#define E_DIM 1024
#define H_DIM 16
#define TB    (T_DIM * B_DIM)          // 16384 rows
#define EPS_RFA 1e-6f

#define BM 128
#define BN 128
#define BK 32
#define NKT (E_DIM / BK)                // 32
#define ROW_B 80
#define ARR_B (128 * ROW_B)
#define STAGE_B (4 * ARR_B)             // 40960
#define NSTAGE 4
#define SM_BIAS 0
#define SM_STAGE0 1024
#define SM_TOTAL (SM_STAGE0 + NSTAGE * STAGE_B)   // 164864

// ------------------------- scratch (static device) -------------------------
__device__ __half g_x_hi[TB * E_DIM];
__device__ __half g_x_lo[TB * E_DIM];
__device__ __half g_Wq_hi[E_DIM * E_DIM];
__device__ __half g_Wq_lo[E_DIM * E_DIM];
__device__ __half g_Wk_hi[E_DIM * E_DIM];
__device__ __half g_Wk_lo[E_DIM * E_DIM];
__device__ __half g_Wv_hi[E_DIM * E_DIM];
__device__ __half g_Wv_lo[E_DIM * E_DIM];
__device__ __nv_bfloat16 g_Wo_hi[E_DIM * E_DIM];
__device__ __nv_bfloat16 g_Wo_lo[E_DIM * E_DIM];
__device__ float g_bq_eff[E_DIM];
__device__ float g_bk_eff[E_DIM];
__device__ float g_v   [TB * E_DIM];
__device__ float g_phiq[(size_t)TB * 2048];
__device__ float g_phik[(size_t)TB * 2048];
__device__ __nv_bfloat16 g_attn_hi[TB * E_DIM];
__device__ __nv_bfloat16 g_attn_lo[TB * E_DIM];

// ----------------------------- PTX helpers ---------------------------------
__device__ __forceinline__ uint32_t smem_to_u32(const void* p) {
    uint32_t a;
    asm("{ .reg .u64 t; cvta.to.shared.u64 t, %1; cvt.u32.u64 %0, t; }" : "=r"(a) : "l"(p));
    return a;
}
__device__ __forceinline__ void cp16(uint32_t dst, const void* src) {
    asm volatile("cp.async.cg.shared.global [%0], [%1], 16;" :: "r"(dst), "l"(src) : "memory");
}
#define CP_COMMIT() asm volatile("cp.async.commit_group;" ::: "memory")
#define CP_WAIT2()  asm volatile("cp.async.wait_group 2;" ::: "memory")

__device__ __forceinline__ void ldsm4(uint32_t* r, uint32_t addr) {
    asm volatile("ldmatrix.sync.aligned.m8n8.x4.shared.b16 {%0,%1,%2,%3}, [%4];"
                 : "=r"(r[0]), "=r"(r[1]), "=r"(r[2]), "=r"(r[3]) : "r"(addr));
}
// accumulate variants (d == c)
__device__ __forceinline__ void mma_f16(float* d, const uint32_t* a, const uint32_t* b) {
    asm volatile(
        "mma.sync.aligned.m16n8k16.row.col.f32.f16.f16.f32 "
        "{%0,%1,%2,%3}, {%4,%5,%6,%7}, {%8,%9}, {%0,%1,%2,%3};"
        : "+f"(d[0]), "+f"(d[1]), "+f"(d[2]), "+f"(d[3])
        : "r"(a[0]), "r"(a[1]), "r"(a[2]), "r"(a[3]), "r"(b[0]), "r"(b[1]));
}
__device__ __forceinline__ void mma_bf16(float* d, const uint32_t* a, const uint32_t* b) {
    asm volatile(
        "mma.sync.aligned.m16n8k16.row.col.f32.bf16.bf16.f32 "
        "{%0,%1,%2,%3}, {%4,%5,%6,%7}, {%8,%9}, {%0,%1,%2,%3};"
        : "+f"(d[0]), "+f"(d[1]), "+f"(d[2]), "+f"(d[3])
        : "r"(a[0]), "r"(a[1]), "r"(a[2]), "r"(a[3]), "r"(b[0]), "r"(b[1]));
}
// zero-C variants (d written fresh, c = 0) — first MMA of each k-chunk
__device__ __forceinline__ void mma_f16_zc(float* d, const uint32_t* a, const uint32_t* b) {
    asm volatile(
        "mma.sync.aligned.m16n8k16.row.col.f32.f16.f16.f32 "
        "{%0,%1,%2,%3}, {%4,%5,%6,%7}, {%8,%9}, {%10,%10,%10,%10};"
        : "=f"(d[0]), "=f"(d[1]), "=f"(d[2]), "=f"(d[3])
        : "r"(a[0]), "r"(a[1]), "r"(a[2]), "r"(a[3]), "r"(b[0]), "r"(b[1]),
          "f"(0.0f));
}
__device__ __forceinline__ void mma_bf16_zc(float* d, const uint32_t* a, const uint32_t* b) {
    asm volatile(
        "mma.sync.aligned.m16n8k16.row.col.f32.bf16.bf16.f32 "
        "{%0,%1,%2,%3}, {%4,%5,%6,%7}, {%8,%9}, {%10,%10,%10,%10};"
        : "=f"(d[0]), "=f"(d[1]), "=f"(d[2]), "=f"(d[3])
        : "r"(a[0]), "r"(a[1]), "r"(a[2]), "r"(a[3]), "r"(b[0]), "r"(b[1]),
          "f"(0.0f));
}

// ---------------------------------------------------------------------------
// fp32 -> fp16 hi/lo split (with pre-scale)
// ---------------------------------------------------------------------------
__global__ void __launch_bounds__(256) f32_to_f16hl(
    const float* __restrict__ in, __half* __restrict__ hi,
    __half* __restrict__ lo, int n, float scale)
{
    int i = (blockIdx.x * 256 + threadIdx.x) * 4;
    if (i >= n) return;
    float4 v = *(const float4*)(in + i);
    float a[4] = {v.x * scale, v.y * scale, v.z * scale, v.w * scale};
    __half h[4], l[4];
#pragma unroll
    for (int j = 0; j < 4; j++) {
        h[j] = __float2half_rn(a[j]);
        l[j] = __float2half_rn(a[j] - __half2float(h[j]));
    }
    *(__half2*)(hi + i)     = __halves2half2(h[0], h[1]);
    *(__half2*)(hi + i + 2) = __halves2half2(h[2], h[3]);
    *(__half2*)(lo + i)     = __halves2half2(l[0], l[1]);
    *(__half2*)(lo + i + 2) = __halves2half2(l[2], l[3]);
}

// fp32 -> bf16 hi/lo split
__global__ void __launch_bounds__(256) f32_to_bf16hl(
    const float* __restrict__ in, __nv_bfloat16* __restrict__ hi,
    __nv_bfloat16* __restrict__ lo, int n)
{
    int i = (blockIdx.x * 256 + threadIdx.x) * 4;
    if (i >= n) return;
    float4 v = *(const float4*)(in + i);
    float a[4] = {v.x, v.y, v.z, v.w};
    __nv_bfloat16 h[4], l[4];
#pragma unroll
    for (int j = 0; j < 4; j++) {
        h[j] = __float2bfloat16(a[j]);
        l[j] = __float2bfloat16(a[j] - __bfloat162float(h[j]));
    }
    *(__nv_bfloat162*)(hi + i)     = __halves2bfloat162(h[0], h[1]);
    *(__nv_bfloat162*)(hi + i + 2) = __halves2bfloat162(h[2], h[3]);
    *(__nv_bfloat162*)(lo + i)     = __halves2bfloat162(l[0], l[1]);
    *(__nv_bfloat162*)(lo + i + 2) = __halves2bfloat162(l[2], l[3]);
}

// ---------------------------------------------------------------------------
// Weight prep: Weff[h*64+k, e] = scale * sum_d rm[h,k,d] * W[h*64+d, e]
// matrix written as fp16 hi/lo with extra x64; beff fp32 (logical scale).
// ---------------------------------------------------------------------------
__global__ void __launch_bounds__(256) prep_weff(
    const float* __restrict__ rm, const float* __restrict__ W,
    const float* __restrict__ bvec, __half* __restrict__ Whi,
    __half* __restrict__ Wlo, float* __restrict__ beff, float scale)
{
    const int h  = blockIdx.y;
    const int e0 = blockIdx.x * 64;
    const int tid = threadIdx.x;

    __shared__ float rs[64][65];
    __shared__ float ws[64][65];

    for (int i = tid; i < 4096; i += 256) {
        int k = i >> 6, dd = i & 63;
        rs[k][dd] = rm[h * 4096 + i];
    }
    for (int i = tid; i < 4096; i += 256) {
        int dd = i >> 6, e = i & 63;
        ws[dd][e] = W[(size_t)(h * 64 + dd) * E_DIM + e0 + e];
    }
    __syncthreads();

    const int tk = (tid >> 4) * 4;
    const int te = (tid & 15) * 4;
    float acc[4][4];
#pragma unroll
    for (int i = 0; i < 4; i++)
#pragma unroll
        for (int j = 0; j < 4; j++) acc[i][j] = 0.f;

#pragma unroll 8
    for (int dd = 0; dd < 64; dd++) {
        float a0 = rs[tk + 0][dd], a1 = rs[tk + 1][dd];
        float a2 = rs[tk + 2][dd], a3 = rs[tk + 3][dd];
        float b0 = ws[dd][te + 0], b1 = ws[dd][te + 1];
        float b2 = ws[dd][te + 2], b3 = ws[dd][te + 3];
        acc[0][0] += a0 * b0; acc[0][1] += a0 * b1; acc[0][2] += a0 * b2; acc[0][3] += a0 * b3;
        acc[1][0] += a1 * b0; acc[1][1] += a1 * b1; acc[1][2] += a1 * b2; acc[1][3] += a1 * b3;
        acc[2][0] += a2 * b0; acc[2][1] += a2 * b1; acc[2][2] += a2 * b2; acc[2][3] += a2 * b3;
        acc[3][0] += a3 * b0; acc[3][1] += a3 * b1; acc[3][2] += a3 * b2; acc[3][3] += a3 * b3;
    }
#pragma unroll
    for (int i = 0; i < 4; i++)
#pragma unroll
        for (int j = 0; j < 4; j++) {
            float val = 64.f * scale * acc[i][j];
            size_t idx = (size_t)(h * 64 + tk + i) * E_DIM + e0 + te + j;
            __half hv = __float2half_rn(val);
            Whi[idx] = hv;
            Wlo[idx] = __float2half_rn(val - __half2float(hv));
        }

    if (blockIdx.x == 0 && tid < 64) {
        float s = 0.f;
        for (int dd = 0; dd < 64; dd++) s += rs[tid][dd] * bvec[h * 64 + dd];
        beff[h * 64 + tid] = scale * s;
    }
}

// ---------------------------------------------------------------------------
// one k-stage loader — 256 threads, 2 iterations (8 cp.async per thread)
// ---------------------------------------------------------------------------
template <typename ET>
__device__ __forceinline__ void load_stage(
    const ET* __restrict__ Ahi, const ET* __restrict__ Alo,
    const ET* __restrict__ Bhi, const ET* __restrict__ Blo,
    int m0, int n0, int kc0, uint32_t st, int tid)
{
#pragma unroll
    for (int i = 0; i < 2; i++) {
        const int idx = tid + 256 * i;
        const int row = idx >> 2;
        const int u = idx & 3;
        const uint32_t doff = row * ROW_B + u * 16;
        const size_t aoff = (size_t)(m0 + row) * E_DIM + kc0 + u * 8;
        const size_t boff = (size_t)(n0 + row) * E_DIM + kc0 + u * 8;
        cp16(st + doff,             Ahi + aoff);
        cp16(st + ARR_B + doff,     Alo + aoff);
        cp16(st + 2 * ARR_B + doff, Bhi + boff);
        cp16(st + 3 * ARR_B + doff, Blo + boff);
    }
}

// ---------------------------------------------------------------------------
// HMMA GEMM: C = escale * (A @ B^T) + bias, 3-term split.
// 256 threads, 8 warps, warp tile 32x64; zero-C chunk starts; drain per chunk;
// 4-stage cp.async ring, prefetch distance 3, single sync per k-iter.
// MODE 0: C fp32, row stride 1024.   MODE 1: phi epilogue, row stride 2048.
// ---------------------------------------------------------------------------
template <int MODE, typename ET>
__global__ void __launch_bounds__(256, 1) tc_gemm(
    const ET* __restrict__ Ahi, const ET* __restrict__ Alo,
    const ET* __restrict__ Bhi, const ET* __restrict__ Blo,
    const float* __restrict__ bias, float* __restrict__ Cout, float escale)
{
    extern __shared__ char smem[];
    const uint32_t sbase = smem_to_u32(smem);
    const int tid = threadIdx.x;
    const int wid = tid >> 5;
    const int lane = tid & 31;
    const int m0 = blockIdx.y * BM;
    const int n0 = blockIdx.x * BN;

    float* bias_s = (float*)(smem + SM_BIAS);
    if (tid < 128) bias_s[tid] = bias[n0 + tid];

    const int wm = wid >> 1;     // 0..3 -> rows wm*32
    const int wn = wid & 1;      // 0..1 -> cols wn*64
    const int g = lane >> 3;
    const int r = lane & 7;

    // preload 3 of 4 stages
#pragma unroll
    for (int s = 0; s < 3; s++) {
        load_stage(Ahi, Alo, Bhi, Blo, m0, n0, s * BK,
                   sbase + SM_STAGE0 + s * STAGE_B, tid);
        CP_COMMIT();
    }

    float accm[2][8][4];
    float accw[2][8][4];
#pragma unroll
    for (int mt = 0; mt < 2; mt++)
#pragma unroll
        for (int j = 0; j < 8; j++)
#pragma unroll
            for (int c = 0; c < 4; c++) accm[mt][j][c] = 0.f;

    const uint32_t a_row_off = (uint32_t)((wm * 32 + (g & 1) * 8 + r) * ROW_B + (g >> 1) * 16);
    const uint32_t b_row_off = (uint32_t)((wn * 64 + (g >> 1) * 8 + r) * ROW_B + (g & 1) * 16);

#pragma unroll 1
    for (int kt = 0; kt < NKT; kt++) {
        CP_WAIT2();        // slot kt%4 ready (its group + <=2 newer outstanding)
        __syncthreads();   // all warps done reading slot (kt-1)%4 == (kt+3)%4

        // refill slot (kt+3)%4 — 3 iterations ahead
        if (kt + 3 < NKT)
            load_stage(Ahi, Alo, Bhi, Blo, m0, n0, (kt + 3) * BK,
                       sbase + SM_STAGE0 + ((kt + 3) % NSTAGE) * STAGE_B, tid);
        CP_COMMIT();

        const uint32_t st = sbase + SM_STAGE0 + (kt % NSTAGE) * STAGE_B;
        const uint32_t sA[2] = { st, st + ARR_B };
        const uint32_t sB[2] = { st + 2 * ARR_B, st + 3 * ARR_B };

#pragma unroll
        for (int ks = 0; ks < 2; ks++) {
            uint32_t afr[2][2][4];   // [mt][hl][4]
            uint32_t bfr[4][2][4];   // [jp][hl][4]
#pragma unroll
            for (int mt = 0; mt < 2; mt++)
#pragma unroll
                for (int hl = 0; hl < 2; hl++)
                    ldsm4(afr[mt][hl], sA[hl] + a_row_off + mt * (16 * ROW_B) + ks * 32);
#pragma unroll
            for (int jp = 0; jp < 4; jp++)
#pragma unroll
                for (int hl = 0; hl < 2; hl++)
                    ldsm4(bfr[jp][hl], sB[hl] + b_row_off + jp * (16 * ROW_B) + ks * 32);

#pragma unroll
            for (int t = 0; t < 3; t++) {
                const int pa = (t == 2) ? 1 : 0;   // hh, hl, lh
                const int pb = (t == 1) ? 1 : 0;
                const bool zc = (ks == 0 && t == 0);   // first write per chunk
#pragma unroll
                for (int mt = 0; mt < 2; mt++)
#pragma unroll
                    for (int j = 0; j < 8; j++) {
                        const uint32_t* bj = &bfr[j >> 1][pb][(j & 1) * 2];
                        if (std::is_same<ET, __half>::value) {
                            if (zc) mma_f16_zc(accw[mt][j], afr[mt][pa], bj);
                            else    mma_f16(accw[mt][j], afr[mt][pa], bj);
                        } else {
                            if (zc) mma_bf16_zc(accw[mt][j], afr[mt][pa], bj);
                            else    mma_bf16(accw[mt][j], afr[mt][pa], bj);
                        }
                    }
            }
        }
        // drain working -> master (IEEE-RN), every chunk (chain length 6)
#pragma unroll
        for (int mt = 0; mt < 2; mt++)
#pragma unroll
            for (int j = 0; j < 8; j++)
#pragma unroll
                for (int c = 0; c < 4; c++) accm[mt][j][c] += accw[mt][j][c];
    }

    // ------------------------------ epilogue --------------------------------
    const int qr = lane >> 2;
    const int qc = (lane & 3) * 2;
#pragma unroll
    for (int mt = 0; mt < 2; mt++) {
        const int row0 = m0 + wm * 32 + mt * 16 + qr;
#pragma unroll
        for (int j = 0; j < 8; j++) {
            const int coll = wn * 64 + j * 8 + qc;
            const int col = n0 + coll;
            const float b0 = bias_s[coll], b1 = bias_s[coll + 1];
            if (MODE == 0) {
                float2 v0 = make_float2(accm[mt][j][0] * escale + b0,
                                        accm[mt][j][1] * escale + b1);
                float2 v1 = make_float2(accm[mt][j][2] * escale + b0,
                                        accm[mt][j][3] * escale + b1);
                *(float2*)(Cout + (size_t)row0 * E_DIM + col) = v0;
                *(float2*)(Cout + (size_t)(row0 + 8) * E_DIM + col) = v1;
            } else {
                const int h = col >> 6, k = col & 63;
                float s0, c0s, s1, c1s, s2, c2s, s3, c3s;
                __sincosf(accm[mt][j][0] * escale + b0, &s0, &c0s);
                __sincosf(accm[mt][j][1] * escale + b1, &s1, &c1s);
                __sincosf(accm[mt][j][2] * escale + b0, &s2, &c2s);
                __sincosf(accm[mt][j][3] * escale + b1, &s3, &c3s);
                float* p0 = Cout + (size_t)row0 * 2048 + h * 128 + k;
                float* p1 = Cout + (size_t)(row0 + 8) * 2048 + h * 128 + k;
                p0[0] = s0 * 0.125f; p0[1]  = s1 * 0.125f;
                p0[64] = c0s * 0.125f; p0[65] = c1s * 0.125f;
                p1[0] = s2 * 0.125f; p1[1]  = s3 * 0.125f;
                p1[64] = c2s * 0.125f; p1[65] = c3s * 0.125f;
            }
        }
    }
}

// ---------------------------------------------------------------------------
// Causal RFA scan. One block per (b,h); 256 threads; ONE sync per timestep.
// attn -> bf16 hi/lo.
// ---------------------------------------------------------------------------
__global__ void __launch_bounds__(256) rfa_scan(
    const float* __restrict__ phiq, const float* __restrict__ phik,
    const float* __restrict__ v, __nv_bfloat16* __restrict__ attn_hi,
    __nv_bfloat16* __restrict__ attn_lo)
{
    const int bx = blockIdx.x;
    const int h = bx & 15;
    const int b = bx >> 4;
    const int tid = threadIdx.x;
    const int d = tid & 63;
    const int kg = tid >> 6;

    __shared__ float s_pq[2][128], s_pk[2][128], s_v[2][64];
    __shared__ float s_z[128];
    __shared__ float s_red[2][256];
    __shared__ float s_qzp[2][4];

    float s_loc[32];
#pragma unroll
    for (int j = 0; j < 32; j++) s_loc[j] = 0.f;
    if (tid < 128) s_z[tid] = 0.f;

    const size_t phi_stride = (size_t)B_DIM * 2048;
    const size_t v_stride   = (size_t)B_DIM * 1024;
    const float* pq_base = phiq + (size_t)b * 2048 + h * 128;
    const float* pk_base = phik + (size_t)b * 2048 + h * 128;
    const float* v_base  = v    + (size_t)b * 1024 + h * 64;
    const size_t o_off   = (size_t)b * 1024 + h * 64;

    float ld_pq = 0.f, ld_pk = 0.f, ld_v = 0.f;
    if (tid < 128) { ld_pq = pq_base[tid]; ld_pk = pk_base[tid]; }
    if (tid < 64)  { ld_v = v_base[tid]; }
    int buf = 0, rb = 0;
    if (tid < 128) { s_pq[0][tid] = ld_pq; s_pk[0][tid] = ld_pk; }
    if (tid < 64)  { s_v[0][tid] = ld_v; }
    __syncthreads();

    for (int t = 0; t < T_DIM; t++) {
        if (t + 1 < T_DIM) {
            if (tid < 128) {
                ld_pq = pq_base[(size_t)(t + 1) * phi_stride + tid];
                ld_pk = pk_base[(size_t)(t + 1) * phi_stride + tid];
            }
            if (tid < 64) ld_v = v_base[(size_t)(t + 1) * v_stride + tid];
        }

        const float vd = s_v[buf][d];
        const float* pkp = &s_pk[buf][kg * 32];
        const float* pqp = &s_pq[buf][kg * 32];
        float acc0 = 0.f, acc1 = 0.f, acc2 = 0.f, acc3 = 0.f;
#pragma unroll
        for (int j = 0; j < 32; j += 4) {
            float4 pk4 = *(const float4*)(pkp + j);
            float4 pq4 = *(const float4*)(pqp + j);
            s_loc[j + 0] += pk4.x * vd; acc0 += pq4.x * s_loc[j + 0];
            s_loc[j + 1] += pk4.y * vd; acc1 += pq4.y * s_loc[j + 1];
            s_loc[j + 2] += pk4.z * vd; acc2 += pq4.z * s_loc[j + 2];
            s_loc[j + 3] += pk4.w * vd; acc3 += pq4.w * s_loc[j + 3];
        }
        s_red[rb][tid] = (acc0 + acc1) + (acc2 + acc3);

        float qzp = 0.f;
        if (tid < 128) {
            float zn = s_z[tid] + s_pk[buf][tid];
            s_z[tid] = zn;
            qzp = s_pq[buf][tid] * zn;
        }
#pragma unroll
        for (int off = 16; off; off >>= 1)
            qzp += __shfl_xor_sync(0xffffffffu, qzp, off);
        if (tid < 128 && (tid & 31) == 0) s_qzp[rb][tid >> 5] = qzp;

        if (t + 1 < T_DIM) {
            if (tid < 128) { s_pq[buf ^ 1][tid] = ld_pq; s_pk[buf ^ 1][tid] = ld_pk; }
            if (tid < 64)  { s_v[buf ^ 1][tid] = ld_v; }
        }

        __syncthreads();

        if (tid < 64) {
            float qs = (s_red[rb][d] + s_red[rb][64 + d]) +
                       (s_red[rb][128 + d] + s_red[rb][192 + d]);
            float qz = (s_qzp[rb][0] + s_qzp[rb][1]) + (s_qzp[rb][2] + s_qzp[rb][3]);
            qz = fmaxf(qz, EPS_RFA);
            float o = qs / qz;
            __nv_bfloat16 hv = __float2bfloat16(o);
            size_t idx = (size_t)t * v_stride + o_off + d;
            attn_hi[idx] = hv;
            attn_lo[idx] = __float2bfloat16(o - __bfloat162float(hv));
        }

        buf ^= 1;
        rb ^= 1;
    }
}

// ---------------------------------------------------------------------------
extern "C" void kernel_launch(void* const* d_in, const int* in_sizes, int n_in,
                              void* d_out, int out_size)
{
    const float* x  = (const float*)d_in[0];
    const float* rm = (const float*)d_in[1];
    const float* Wq = (const float*)d_in[2];
    const float* bq = (const float*)d_in[3];
    const float* Wk = (const float*)d_in[4];
    const float* bk = (const float*)d_in[5];
    const float* Wv = (const float*)d_in[6];
    const float* bv = (const float*)d_in[7];
    const float* Wo = (const float*)d_in[8];
    const float* bo = (const float*)d_in[9];
    float* out = (float*)d_out;

    __half *x_hi, *x_lo, *Wq_hi, *Wq_lo, *Wk_hi, *Wk_lo, *Wv_hi, *Wv_lo;
    __nv_bfloat16 *Wo_hi, *Wo_lo, *attn_hi, *attn_lo;
    float *bq_eff, *bk_eff, *vbuf, *phiq, *phik;
    cudaGetSymbolAddress((void**)&x_hi, g_x_hi);
    cudaGetSymbolAddress((void**)&x_lo, g_x_lo);
    cudaGetSymbolAddress((void**)&Wq_hi, g_Wq_hi);
    cudaGetSymbolAddress((void**)&Wq_lo, g_Wq_lo);
    cudaGetSymbolAddress((void**)&Wk_hi, g_Wk_hi);
    cudaGetSymbolAddress((void**)&Wk_lo, g_Wk_lo);
    cudaGetSymbolAddress((void**)&Wv_hi, g_Wv_hi);
    cudaGetSymbolAddress((void**)&Wv_lo, g_Wv_lo);
    cudaGetSymbolAddress((void**)&Wo_hi, g_Wo_hi);
    cudaGetSymbolAddress((void**)&Wo_lo, g_Wo_lo);
    cudaGetSymbolAddress((void**)&attn_hi, g_attn_hi);
    cudaGetSymbolAddress((void**)&attn_lo, g_attn_lo);
    cudaGetSymbolAddress((void**)&bq_eff, g_bq_eff);
    cudaGetSymbolAddress((void**)&bk_eff, g_bk_eff);
    cudaGetSymbolAddress((void**)&vbuf, g_v);
    cudaGetSymbolAddress((void**)&phiq, g_phiq);
    cudaGetSymbolAddress((void**)&phik, g_phik);

    cudaFuncSetAttribute((const void*)tc_gemm<0, __half>,
                         cudaFuncAttributeMaxDynamicSharedMemorySize, SM_TOTAL);
    cudaFuncSetAttribute((const void*)tc_gemm<1, __half>,
                         cudaFuncAttributeMaxDynamicSharedMemorySize, SM_TOTAL);
    cudaFuncSetAttribute((const void*)tc_gemm<0, __nv_bfloat16>,
                         cudaFuncAttributeMaxDynamicSharedMemorySize, SM_TOTAL);

    // conversions + weight prep: x scaled x256 (fp16 lo stays normal),
    // fp16 weights x64; bf16 Wo unscaled.
    f32_to_f16hl<<<TB * E_DIM / 1024, 256>>>(x, x_hi, x_lo, TB * E_DIM, 256.0f);
    prep_weff<<<dim3(16, 16), 256>>>(rm, Wq, bq, Wq_hi, Wq_lo, bq_eff, 0.125f);
    prep_weff<<<dim3(16, 16), 256>>>(rm, Wk, bk, Wk_hi, Wk_lo, bk_eff, 1.0f);
    f32_to_f16hl<<<E_DIM * E_DIM / 1024, 256>>>(Wv, Wv_hi, Wv_lo, E_DIM * E_DIM, 64.0f);
    f32_to_bf16hl<<<E_DIM * E_DIM / 1024, 256>>>(Wo, Wo_hi, Wo_lo, E_DIM * E_DIM);

    // tensor-core GEMMs (escale undoes x256 * x64)
    dim3 gg(E_DIM / BN, TB / BM);   // (8, 128)
    const float inv = 1.0f / 16384.0f;
    tc_gemm<1, __half><<<gg, 256, SM_TOTAL>>>(x_hi, x_lo, Wq_hi, Wq_lo, bq_eff, phiq, inv);
    tc_gemm<1, __half><<<gg, 256, SM_TOTAL>>>(x_hi, x_lo, Wk_hi, Wk_lo, bk_eff, phik, inv);
    tc_gemm<0, __half><<<gg, 256, SM_TOTAL>>>(x_hi, x_lo, Wv_hi, Wv_lo, bv, vbuf, inv);

    // causal scan (writes attn bf16 split)
    rfa_scan<<<B_DIM * H_DIM, 256>>>(phiq, phik, vbuf, attn_hi, attn_lo);

    // output projection (bf16 split, unamplified error path)
    tc_gemm<0, __nv_bfloat16><<<gg, 256, SM_TOTAL>>>(attn_hi, attn_lo, Wo_hi, Wo_lo, bo, out, 1.0f);
}

// round 10
// speedup vs baseline: 1.0839x; 1.0747x over previous
#include <cuda_runtime.h>
#include <cuda_fp16.h>
#include <cuda_bf16.h>
#include <cstdint>
#include <type_traits>

// ---------------------------------------------------------------------------
// CausalAttention (random-feature attention) — mma.sync 3-term split GEMMs
// (zero-C chunk starts, per-chunk RN drain, 4-stage cp.async ring) +
// d-split x2 causal scan (256 blocks, R6-proven 2-sync structure).
// ---------------------------------------------------------------------------

#define T_DIM 2048
#define B_DIM 8
#define E_DIM 1024
#define H_DIM 16
#define TB    (T_DIM * B_DIM)          // 16384 rows
#define EPS_RFA 1e-6f

#define BM 128
#define BN 128
#define BK 32
#define NKT (E_DIM / BK)                // 32
#define ROW_B 80
#define ARR_B (128 * ROW_B)
#define STAGE_B (4 * ARR_B)             // 40960
#define NSTAGE 4
#define SM_BIAS 0
#define SM_STAGE0 1024
#define SM_TOTAL (SM_STAGE0 + NSTAGE * STAGE_B)   // 164864

// ------------------------- scratch (static device) -------------------------
__device__ __half g_x_hi[TB * E_DIM];
__device__ __half g_x_lo[TB * E_DIM];
__device__ __half g_Wq_hi[E_DIM * E_DIM];
__device__ __half g_Wq_lo[E_DIM * E_DIM];
__device__ __half g_Wk_hi[E_DIM * E_DIM];
__device__ __half g_Wk_lo[E_DIM * E_DIM];
__device__ __half g_Wv_hi[E_DIM * E_DIM];
__device__ __half g_Wv_lo[E_DIM * E_DIM];
__device__ __nv_bfloat16 g_Wo_hi[E_DIM * E_DIM];
__device__ __nv_bfloat16 g_Wo_lo[E_DIM * E_DIM];
__device__ float g_bq_eff[E_DIM];
__device__ float g_bk_eff[E_DIM];
__device__ float g_v   [TB * E_DIM];
__device__ float g_phiq[(size_t)TB * 2048];
__device__ float g_phik[(size_t)TB * 2048];
__device__ __nv_bfloat16 g_attn_hi[TB * E_DIM];
__device__ __nv_bfloat16 g_attn_lo[TB * E_DIM];

// ----------------------------- PTX helpers ---------------------------------
__device__ __forceinline__ uint32_t smem_to_u32(const void* p) {
    uint32_t a;
    asm("{ .reg .u64 t; cvta.to.shared.u64 t, %1; cvt.u32.u64 %0, t; }" : "=r"(a) : "l"(p));
    return a;
}
__device__ __forceinline__ void cp16(uint32_t dst, const void* src) {
    asm volatile("cp.async.cg.shared.global [%0], [%1], 16;" :: "r"(dst), "l"(src) : "memory");
}
#define CP_COMMIT() asm volatile("cp.async.commit_group;" ::: "memory")
#define CP_WAIT2()  asm volatile("cp.async.wait_group 2;" ::: "memory")

__device__ __forceinline__ void ldsm4(uint32_t* r, uint32_t addr) {
    asm volatile("ldmatrix.sync.aligned.m8n8.x4.shared.b16 {%0,%1,%2,%3}, [%4];"
                 : "=r"(r[0]), "=r"(r[1]), "=r"(r[2]), "=r"(r[3]) : "r"(addr));
}
// accumulate variants (d == c)
__device__ __forceinline__ void mma_f16(float* d, const uint32_t* a, const uint32_t* b) {
    asm volatile(
        "mma.sync.aligned.m16n8k16.row.col.f32.f16.f16.f32 "
        "{%0,%1,%2,%3}, {%4,%5,%6,%7}, {%8,%9}, {%0,%1,%2,%3};"
        : "+f"(d[0]), "+f"(d[1]), "+f"(d[2]), "+f"(d[3])
        : "r"(a[0]), "r"(a[1]), "r"(a[2]), "r"(a[3]), "r"(b[0]), "r"(b[1]));
}
__device__ __forceinline__ void mma_bf16(float* d, const uint32_t* a, const uint32_t* b) {
    asm volatile(
        "mma.sync.aligned.m16n8k16.row.col.f32.bf16.bf16.f32 "
        "{%0,%1,%2,%3}, {%4,%5,%6,%7}, {%8,%9}, {%0,%1,%2,%3};"
        : "+f"(d[0]), "+f"(d[1]), "+f"(d[2]), "+f"(d[3])
        : "r"(a[0]), "r"(a[1]), "r"(a[2]), "r"(a[3]), "r"(b[0]), "r"(b[1]));
}
// zero-C variants (d written fresh, c = 0) — first MMA of each k-chunk
__device__ __forceinline__ void mma_f16_zc(float* d, const uint32_t* a, const uint32_t* b) {
    asm volatile(
        "mma.sync.aligned.m16n8k16.row.col.f32.f16.f16.f32 "
        "{%0,%1,%2,%3}, {%4,%5,%6,%7}, {%8,%9}, {%10,%10,%10,%10};"
        : "=f"(d[0]), "=f"(d[1]), "=f"(d[2]), "=f"(d[3])
        : "r"(a[0]), "r"(a[1]), "r"(a[2]), "r"(a[3]), "r"(b[0]), "r"(b[1]),
          "f"(0.0f));
}
__device__ __forceinline__ void mma_bf16_zc(float* d, const uint32_t* a, const uint32_t* b) {
    asm volatile(
        "mma.sync.aligned.m16n8k16.row.col.f32.bf16.bf16.f32 "
        "{%0,%1,%2,%3}, {%4,%5,%6,%7}, {%8,%9}, {%10,%10,%10,%10};"
        : "=f"(d[0]), "=f"(d[1]), "=f"(d[2]), "=f"(d[3])
        : "r"(a[0]), "r"(a[1]), "r"(a[2]), "r"(a[3]), "r"(b[0]), "r"(b[1]),
          "f"(0.0f));
}

// ---------------------------------------------------------------------------
// fp32 -> fp16 hi/lo split (with pre-scale)
// ---------------------------------------------------------------------------
__global__ void __launch_bounds__(256) f32_to_f16hl(
    const float* __restrict__ in, __half* __restrict__ hi,
    __half* __restrict__ lo, int n, float scale)
{
    int i = (blockIdx.x * 256 + threadIdx.x) * 4;
    if (i >= n) return;
    float4 v = *(const float4*)(in + i);
    float a[4] = {v.x * scale, v.y * scale, v.z * scale, v.w * scale};
    __half h[4], l[4];
#pragma unroll
    for (int j = 0; j < 4; j++) {
        h[j] = __float2half_rn(a[j]);
        l[j] = __float2half_rn(a[j] - __half2float(h[j]));
    }
    *(__half2*)(hi + i)     = __halves2half2(h[0], h[1]);
    *(__half2*)(hi + i + 2) = __halves2half2(h[2], h[3]);
    *(__half2*)(lo + i)     = __halves2half2(l[0], l[1]);
    *(__half2*)(lo + i + 2) = __halves2half2(l[2], l[3]);
}

// fp32 -> bf16 hi/lo split
__global__ void __launch_bounds__(256) f32_to_bf16hl(
    const float* __restrict__ in, __nv_bfloat16* __restrict__ hi,
    __nv_bfloat16* __restrict__ lo, int n)
{
    int i = (blockIdx.x * 256 + threadIdx.x) * 4;
    if (i >= n) return;
    float4 v = *(const float4*)(in + i);
    float a[4] = {v.x, v.y, v.z, v.w};
    __nv_bfloat16 h[4], l[4];
#pragma unroll
    for (int j = 0; j < 4; j++) {
        h[j] = __float2bfloat16(a[j]);
        l[j] = __float2bfloat16(a[j] - __bfloat162float(h[j]));
    }
    *(__nv_bfloat162*)(hi + i)     = __halves2bfloat162(h[0], h[1]);
    *(__nv_bfloat162*)(hi + i + 2) = __halves2bfloat162(h[2], h[3]);
    *(__nv_bfloat162*)(lo + i)     = __halves2bfloat162(l[0], l[1]);
    *(__nv_bfloat162*)(lo + i + 2) = __halves2bfloat162(l[2], l[3]);
}

// ---------------------------------------------------------------------------
// Weight prep: Weff[h*64+k, e] = scale * sum_d rm[h,k,d] * W[h*64+d, e]
// matrix written as fp16 hi/lo with extra x64; beff fp32 (logical scale).
// ---------------------------------------------------------------------------
__global__ void __launch_bounds__(256) prep_weff(
    const float* __restrict__ rm, const float* __restrict__ W,
    const float* __restrict__ bvec, __half* __restrict__ Whi,
    __half* __restrict__ Wlo, float* __restrict__ beff, float scale)
{
    const int h  = blockIdx.y;
    const int e0 = blockIdx.x * 64;
    const int tid = threadIdx.x;

    __shared__ float rs[64][65];
    __shared__ float ws[64][65];

    for (int i = tid; i < 4096; i += 256) {
        int k = i >> 6, dd = i & 63;
        rs[k][dd] = rm[h * 4096 + i];
    }
    for (int i = tid; i < 4096; i += 256) {
        int dd = i >> 6, e = i & 63;
        ws[dd][e] = W[(size_t)(h * 64 + dd) * E_DIM + e0 + e];
    }
    __syncthreads();

    const int tk = (tid >> 4) * 4;
    const int te = (tid & 15) * 4;
    float acc[4][4];
#pragma unroll
    for (int i = 0; i < 4; i++)
#pragma unroll
        for (int j = 0; j < 4; j++) acc[i][j] = 0.f;

#pragma unroll 8
    for (int dd = 0; dd < 64; dd++) {
        float a0 = rs[tk + 0][dd], a1 = rs[tk + 1][dd];
        float a2 = rs[tk + 2][dd], a3 = rs[tk + 3][dd];
        float b0 = ws[dd][te + 0], b1 = ws[dd][te + 1];
        float b2 = ws[dd][te + 2], b3 = ws[dd][te + 3];
        acc[0][0] += a0 * b0; acc[0][1] += a0 * b1; acc[0][2] += a0 * b2; acc[0][3] += a0 * b3;
        acc[1][0] += a1 * b0; acc[1][1] += a1 * b1; acc[1][2] += a1 * b2; acc[1][3] += a1 * b3;
        acc[2][0] += a2 * b0; acc[2][1] += a2 * b1; acc[2][2] += a2 * b2; acc[2][3] += a2 * b3;
        acc[3][0] += a3 * b0; acc[3][1] += a3 * b1; acc[3][2] += a3 * b2; acc[3][3] += a3 * b3;
    }
#pragma unroll
    for (int i = 0; i < 4; i++)
#pragma unroll
        for (int j = 0; j < 4; j++) {
            float val = 64.f * scale * acc[i][j];
            size_t idx = (size_t)(h * 64 + tk + i) * E_DIM + e0 + te + j;
            __half hv = __float2half_rn(val);
            Whi[idx] = hv;
            Wlo[idx] = __float2half_rn(val - __half2float(hv));
        }

    if (blockIdx.x == 0 && tid < 64) {
        float s = 0.f;
        for (int dd = 0; dd < 64; dd++) s += rs[tid][dd] * bvec[h * 64 + dd];
        beff[h * 64 + tid] = scale * s;
    }
}

// ---------------------------------------------------------------------------
// one k-stage loader — 256 threads, 2 iterations (8 cp.async per thread)
// ---------------------------------------------------------------------------
template <typename ET>
__device__ __forceinline__ void load_stage(
    const ET* __restrict__ Ahi, const ET* __restrict__ Alo,
    const ET* __restrict__ Bhi, const ET* __restrict__ Blo,
    int m0, int n0, int kc0, uint32_t st, int tid)
{
#pragma unroll
    for (int i = 0; i < 2; i++) {
        const int idx = tid + 256 * i;
        const int row = idx >> 2;
        const int u = idx & 3;
        const uint32_t doff = row * ROW_B + u * 16;
        const size_t aoff = (size_t)(m0 + row) * E_DIM + kc0 + u * 8;
        const size_t boff = (size_t)(n0 + row) * E_DIM + kc0 + u * 8;
        cp16(st + doff,             Ahi + aoff);
        cp16(st + ARR_B + doff,     Alo + aoff);
        cp16(st + 2 * ARR_B + doff, Bhi + boff);
        cp16(st + 3 * ARR_B + doff, Blo + boff);
    }
}

// ---------------------------------------------------------------------------
// HMMA GEMM: C = escale * (A @ B^T) + bias, 3-term split.
// 256 threads, 8 warps, warp tile 32x64; zero-C chunk starts; drain per chunk;
// 4-stage cp.async ring, prefetch distance 3, single sync per k-iter.
// MODE 0: C fp32, row stride 1024.   MODE 1: phi epilogue, row stride 2048.
// ---------------------------------------------------------------------------
template <int MODE, typename ET>
__global__ void __launch_bounds__(256, 1) tc_gemm(
    const ET* __restrict__ Ahi, const ET* __restrict__ Alo,
    const ET* __restrict__ Bhi, const ET* __restrict__ Blo,
    const float* __restrict__ bias, float* __restrict__ Cout, float escale)
{
    extern __shared__ char smem[];
    const uint32_t sbase = smem_to_u32(smem);
    const int tid = threadIdx.x;
    const int wid = tid >> 5;
    const int lane = tid & 31;
    const int m0 = blockIdx.y * BM;
    const int n0 = blockIdx.x * BN;

    float* bias_s = (float*)(smem + SM_BIAS);
    if (tid < 128) bias_s[tid] = bias[n0 + tid];

    const int wm = wid >> 1;     // 0..3 -> rows wm*32
    const int wn = wid & 1;      // 0..1 -> cols wn*64
    const int g = lane >> 3;
    const int r = lane & 7;

    // preload 3 of 4 stages
#pragma unroll
    for (int s = 0; s < 3; s++) {
        load_stage(Ahi, Alo, Bhi, Blo, m0, n0, s * BK,
                   sbase + SM_STAGE0 + s * STAGE_B, tid);
        CP_COMMIT();
    }

    float accm[2][8][4];
    float accw[2][8][4];
#pragma unroll
    for (int mt = 0; mt < 2; mt++)
#pragma unroll
        for (int j = 0; j < 8; j++)
#pragma unroll
            for (int c = 0; c < 4; c++) accm[mt][j][c] = 0.f;

    const uint32_t a_row_off = (uint32_t)((wm * 32 + (g & 1) * 8 + r) * ROW_B + (g >> 1) * 16);
    const uint32_t b_row_off = (uint32_t)((wn * 64 + (g >> 1) * 8 + r) * ROW_B + (g & 1) * 16);

#pragma unroll 1
    for (int kt = 0; kt < NKT; kt++) {
        CP_WAIT2();        // slot kt%4 ready (its group + <=2 newer outstanding)
        __syncthreads();   // all warps done reading slot (kt-1)%4 == (kt+3)%4

        // refill slot (kt+3)%4 — 3 iterations ahead
        if (kt + 3 < NKT)
            load_stage(Ahi, Alo, Bhi, Blo, m0, n0, (kt + 3) * BK,
                       sbase + SM_STAGE0 + ((kt + 3) % NSTAGE) * STAGE_B, tid);
        CP_COMMIT();

        const uint32_t st = sbase + SM_STAGE0 + (kt % NSTAGE) * STAGE_B;
        const uint32_t sA[2] = { st, st + ARR_B };
        const uint32_t sB[2] = { st + 2 * ARR_B, st + 3 * ARR_B };

#pragma unroll
        for (int ks = 0; ks < 2; ks++) {
            uint32_t afr[2][2][4];   // [mt][hl][4]
            uint32_t bfr[4][2][4];   // [jp][hl][4]
#pragma unroll
            for (int mt = 0; mt < 2; mt++)
#pragma unroll
                for (int hl = 0; hl < 2; hl++)
                    ldsm4(afr[mt][hl], sA[hl] + a_row_off + mt * (16 * ROW_B) + ks * 32);
#pragma unroll
            for (int jp = 0; jp < 4; jp++)
#pragma unroll
                for (int hl = 0; hl < 2; hl++)
                    ldsm4(bfr[jp][hl], sB[hl] + b_row_off + jp * (16 * ROW_B) + ks * 32);

#pragma unroll
            for (int t = 0; t < 3; t++) {
                const int pa = (t == 2) ? 1 : 0;   // hh, hl, lh
                const int pb = (t == 1) ? 1 : 0;
                const bool zc = (ks == 0 && t == 0);   // first write per chunk
#pragma unroll
                for (int mt = 0; mt < 2; mt++)
#pragma unroll
                    for (int j = 0; j < 8; j++) {
                        const uint32_t* bj = &bfr[j >> 1][pb][(j & 1) * 2];
                        if (std::is_same<ET, __half>::value) {
                            if (zc) mma_f16_zc(accw[mt][j], afr[mt][pa], bj);
                            else    mma_f16(accw[mt][j], afr[mt][pa], bj);
                        } else {
                            if (zc) mma_bf16_zc(accw[mt][j], afr[mt][pa], bj);
                            else    mma_bf16(accw[mt][j], afr[mt][pa], bj);
                        }
                    }
            }
        }
        // drain working -> master (IEEE-RN), every chunk (chain length 6)
#pragma unroll
        for (int mt = 0; mt < 2; mt++)
#pragma unroll
            for (int j = 0; j < 8; j++)
#pragma unroll
                for (int c = 0; c < 4; c++) accm[mt][j][c] += accw[mt][j][c];
    }

    // ------------------------------ epilogue --------------------------------
    const int qr = lane >> 2;
    const int qc = (lane & 3) * 2;
#pragma unroll
    for (int mt = 0; mt < 2; mt++) {
        const int row0 = m0 + wm * 32 + mt * 16 + qr;
#pragma unroll
        for (int j = 0; j < 8; j++) {
            const int coll = wn * 64 + j * 8 + qc;
            const int col = n0 + coll;
            const float b0 = bias_s[coll], b1 = bias_s[coll + 1];
            if (MODE == 0) {
                float2 v0 = make_float2(accm[mt][j][0] * escale + b0,
                                        accm[mt][j][1] * escale + b1);
                float2 v1 = make_float2(accm[mt][j][2] * escale + b0,
                                        accm[mt][j][3] * escale + b1);
                *(float2*)(Cout + (size_t)row0 * E_DIM + col) = v0;
                *(float2*)(Cout + (size_t)(row0 + 8) * E_DIM + col) = v1;
            } else {
                const int h = col >> 6, k = col & 63;
                float s0, c0s, s1, c1s, s2, c2s, s3, c3s;
                __sincosf(accm[mt][j][0] * escale + b0, &s0, &c0s);
                __sincosf(accm[mt][j][1] * escale + b1, &s1, &c1s);
                __sincosf(accm[mt][j][2] * escale + b0, &s2, &c2s);
                __sincosf(accm[mt][j][3] * escale + b1, &s3, &c3s);
                float* p0 = Cout + (size_t)row0 * 2048 + h * 128 + k;
                float* p1 = Cout + (size_t)(row0 + 8) * 2048 + h * 128 + k;
                p0[0] = s0 * 0.125f; p0[1]  = s1 * 0.125f;
                p0[64] = c0s * 0.125f; p0[65] = c1s * 0.125f;
                p1[0] = s2 * 0.125f; p1[1]  = s3 * 0.125f;
                p1[64] = c2s * 0.125f; p1[65] = c3s * 0.125f;
            }
        }
    }
}

// ---------------------------------------------------------------------------
// Causal RFA scan, d-split x2: block bx = bh*2 + dh handles output dims
// d in [dh*32, dh*32+32). 256 threads: dl = tid&31, kg = tid>>5 (8 k-groups
// of 16 k). Thread owns s[kg*16+j][dh*32+dl], j=0..15. R6-proven 2-sync
// structure. attn -> bf16 hi/lo.
// ---------------------------------------------------------------------------
__global__ void __launch_bounds__(256) rfa_scan(
    const float* __restrict__ phiq, const float* __restrict__ phik,
    const float* __restrict__ v, __nv_bfloat16* __restrict__ attn_hi,
    __nv_bfloat16* __restrict__ attn_lo)
{
    const int bx = blockIdx.x;       // bh*2 + dh
    const int dh = bx & 1;
    const int bh = bx >> 1;
    const int h = bh & 15;
    const int b = bh >> 4;
    const int tid = threadIdx.x;
    const int dl = tid & 31;
    const int kg = tid >> 5;         // 0..7

    __shared__ float s_pq[2][128], s_pk[2][128], s_v[2][32];
    __shared__ float s_z[128];
    __shared__ float s_red[256];
    __shared__ float s_qzp[4];

    float s_loc[16];
#pragma unroll
    for (int j = 0; j < 16; j++) s_loc[j] = 0.f;
    if (tid < 128) s_z[tid] = 0.f;

    const size_t phi_stride = (size_t)B_DIM * 2048;
    const size_t v_stride   = (size_t)B_DIM * 1024;
    const float* pq_base = phiq + (size_t)b * 2048 + h * 128;
    const float* pk_base = phik + (size_t)b * 2048 + h * 128;
    const float* v_base  = v    + (size_t)b * 1024 + h * 64 + dh * 32;
    const size_t o_off   = (size_t)b * 1024 + h * 64 + dh * 32;

    float ld_pq = 0.f, ld_pk = 0.f, ld_v = 0.f;
    if (tid < 128) { ld_pq = pq_base[tid]; ld_pk = pk_base[tid]; }
    if (tid < 32)  { ld_v = v_base[tid]; }
    int buf = 0;
    if (tid < 128) { s_pq[0][tid] = ld_pq; s_pk[0][tid] = ld_pk; }
    if (tid < 32)  { s_v[0][tid] = ld_v; }
    __syncthreads();

    for (int t = 0; t < T_DIM; t++) {
        // prefetch t+1 (gmem -> regs)
        if (t + 1 < T_DIM) {
            if (tid < 128) {
                ld_pq = pq_base[(size_t)(t + 1) * phi_stride + tid];
                ld_pk = pk_base[(size_t)(t + 1) * phi_stride + tid];
            }
            if (tid < 32) ld_v = v_base[(size_t)(t + 1) * v_stride + tid];
        }

        // s update + q.s partials (16 k's of this thread's kg slice)
        const float vd = s_v[buf][dl];
        const float* pkp = &s_pk[buf][kg * 16];
        const float* pqp = &s_pq[buf][kg * 16];
        float acc0 = 0.f, acc1 = 0.f, acc2 = 0.f, acc3 = 0.f;
#pragma unroll
        for (int j = 0; j < 16; j += 4) {
            float4 pk4 = *(const float4*)(pkp + j);
            float4 pq4 = *(const float4*)(pqp + j);
            s_loc[j + 0] += pk4.x * vd; acc0 += pq4.x * s_loc[j + 0];
            s_loc[j + 1] += pk4.y * vd; acc1 += pq4.y * s_loc[j + 1];
            s_loc[j + 2] += pk4.z * vd; acc2 += pq4.z * s_loc[j + 2];
            s_loc[j + 3] += pk4.w * vd; acc3 += pq4.w * s_loc[j + 3];
        }
        s_red[tid] = (acc0 + acc1) + (acc2 + acc3);

        // z update + qz partials (threads 0..127, one per k)
        float qzp = 0.f;
        if (tid < 128) {
            float zn = s_z[tid] + s_pk[buf][tid];
            s_z[tid] = zn;
            qzp = s_pq[buf][tid] * zn;
        }
#pragma unroll
        for (int off = 16; off; off >>= 1)
            qzp += __shfl_xor_sync(0xffffffffu, qzp, off);
        if (tid < 128 && (tid & 31) == 0) s_qzp[tid >> 5] = qzp;
        __syncthreads();

        // finalize + write attn[t] for this block's 32 d's
        if (tid < 32) {
            float qs = ((s_red[dl] + s_red[32 + dl]) +
                        (s_red[64 + dl] + s_red[96 + dl])) +
                       ((s_red[128 + dl] + s_red[160 + dl]) +
                        (s_red[192 + dl] + s_red[224 + dl]));
            float qz = (s_qzp[0] + s_qzp[1]) + (s_qzp[2] + s_qzp[3]);
            qz = fmaxf(qz, EPS_RFA);
            float o = qs / qz;
            __nv_bfloat16 hv = __float2bfloat16(o);
            size_t idx = (size_t)t * v_stride + o_off + dl;
            attn_hi[idx] = hv;
            attn_lo[idx] = __float2bfloat16(o - __bfloat162float(hv));
        }

        // stage prefetched row into the other buffer
        buf ^= 1;
        if (t + 1 < T_DIM) {
            if (tid < 128) { s_pq[buf][tid] = ld_pq; s_pk[buf][tid] = ld_pk; }
            if (tid < 32)  { s_v[buf][tid] = ld_v; }
        }
        __syncthreads();
    }
}

// ---------------------------------------------------------------------------
extern "C" void kernel_launch(void* const* d_in, const int* in_sizes, int n_in,
                              void* d_out, int out_size)
{
    const float* x  = (const float*)d_in[0];
    const float* rm = (const float*)d_in[1];
    const float* Wq = (const float*)d_in[2];
    const float* bq = (const float*)d_in[3];
    const float* Wk = (const float*)d_in[4];
    const float* bk = (const float*)d_in[5];
    const float* Wv = (const float*)d_in[6];
    const float* bv = (const float*)d_in[7];
    const float* Wo = (const float*)d_in[8];
    const float* bo = (const float*)d_in[9];
    float* out = (float*)d_out;

    __half *x_hi, *x_lo, *Wq_hi, *Wq_lo, *Wk_hi, *Wk_lo, *Wv_hi, *Wv_lo;
    __nv_bfloat16 *Wo_hi, *Wo_lo, *attn_hi, *attn_lo;
    float *bq_eff, *bk_eff, *vbuf, *phiq, *phik;
    cudaGetSymbolAddress((void**)&x_hi, g_x_hi);
    cudaGetSymbolAddress((void**)&x_lo, g_x_lo);
    cudaGetSymbolAddress((void**)&Wq_hi, g_Wq_hi);
    cudaGetSymbolAddress((void**)&Wq_lo, g_Wq_lo);
    cudaGetSymbolAddress((void**)&Wk_hi, g_Wk_hi);
    cudaGetSymbolAddress((void**)&Wk_lo, g_Wk_lo);
    cudaGetSymbolAddress((void**)&Wv_hi, g_Wv_hi);
    cudaGetSymbolAddress((void**)&Wv_lo, g_Wv_lo);
    cudaGetSymbolAddress((void**)&Wo_hi, g_Wo_hi);
    cudaGetSymbolAddress((void**)&Wo_lo, g_Wo_lo);
    cudaGetSymbolAddress((void**)&attn_hi, g_attn_hi);
    cudaGetSymbolAddress((void**)&attn_lo, g_attn_lo);
    cudaGetSymbolAddress((void**)&bq_eff, g_bq_eff);
    cudaGetSymbolAddress((void**)&bk_eff, g_bk_eff);
    cudaGetSymbolAddress((void**)&vbuf, g_v);
    cudaGetSymbolAddress((void**)&phiq, g_phiq);
    cudaGetSymbolAddress((void**)&phik, g_phik);

    cudaFuncSetAttribute((const void*)tc_gemm<0, __half>,
                         cudaFuncAttributeMaxDynamicSharedMemorySize, SM_TOTAL);
    cudaFuncSetAttribute((const void*)tc_gemm<1, __half>,
                         cudaFuncAttributeMaxDynamicSharedMemorySize, SM_TOTAL);
    cudaFuncSetAttribute((const void*)tc_gemm<0, __nv_bfloat16>,
                         cudaFuncAttributeMaxDynamicSharedMemorySize, SM_TOTAL);

    // conversions + weight prep: x scaled x256 (fp16 lo stays normal),
    // fp16 weights x64; bf16 Wo unscaled.
    f32_to_f16hl<<<TB * E_DIM / 1024, 256>>>(x, x_hi, x_lo, TB * E_DIM, 256.0f);
    prep_weff<<<dim3(16, 16), 256>>>(rm, Wq, bq, Wq_hi, Wq_lo, bq_eff, 0.125f);
    prep_weff<<<dim3(16, 16), 256>>>(rm, Wk, bk, Wk_hi, Wk_lo, bk_eff, 1.0f);
    f32_to_f16hl<<<E_DIM * E_DIM / 1024, 256>>>(Wv, Wv_hi, Wv_lo, E_DIM * E_DIM, 64.0f);
    f32_to_bf16hl<<<E_DIM * E_DIM / 1024, 256>>>(Wo, Wo_hi, Wo_lo, E_DIM * E_DIM);

    // tensor-core GEMMs (escale undoes x256 * x64)
    dim3 gg(E_DIM / BN, TB / BM);   // (8, 128)
    const float inv = 1.0f / 16384.0f;
    tc_gemm<1, __half><<<gg, 256, SM_TOTAL>>>(x_hi, x_lo, Wq_hi, Wq_lo, bq_eff, phiq, inv);
    tc_gemm<1, __half><<<gg, 256, SM_TOTAL>>>(x_hi, x_lo, Wk_hi, Wk_lo, bk_eff, phik, inv);
    tc_gemm<0, __half><<<gg, 256, SM_TOTAL>>>(x_hi, x_lo, Wv_hi, Wv_lo, bv, vbuf, inv);

    // causal scan, d-split x2 (256 blocks; writes attn bf16 split)
    rfa_scan<<<B_DIM * H_DIM * 2, 256>>>(phiq, phik, vbuf, attn_hi, attn_lo);

    // output projection (bf16 split, unamplified error path)
    tc_gemm<0, __nv_bfloat16><<<gg, 256, SM_TOTAL>>>(attn_hi, attn_lo, Wo_hi, Wo_lo, bo, out, 1.0f);
}

// round 11
// speedup vs baseline: 1.2750x; 1.1762x over previous
#include <cuda_runtime.h>
#include <cuda_fp16.h>
#include <cuda_bf16.h>
#include <cstdint>
#include <type_traits>

// ---------------------------------------------------------------------------
// CausalAttention (random-feature attention) — mma.sync 3-term split GEMMs
// (zero-C chunk starts, RN drain: every chunk on phi GEMMs, every 2 on v/out)
// + d-split x2, 2-timesteps-per-iteration causal scan (R6 2-sync skeleton).
// ---------------------------------------------------------------------------

#define T_DIM 2048
#define B_DIM 8
#define E_DIM 1024
#define H_DIM 16
#define TB    (T_DIM * B_DIM)          // 16384 rows
#define EPS_RFA 1e-6f

#define BM 128
#define BN 128
#define BK 32
#define NKT (E_DIM / BK)                // 32
#define ROW_B 80
#define ARR_B (128 * ROW_B)
#define STAGE_B (4 * ARR_B)             // 40960
#define NSTAGE 4
#define SM_BIAS 0
#define SM_STAGE0 1024
#define SM_TOTAL (SM_STAGE0 + NSTAGE * STAGE_B)   // 164864

// ------------------------- scratch (static device) -------------------------
__device__ __half g_x_hi[TB * E_DIM];
__device__ __half g_x_lo[TB * E_DIM];
__device__ __half g_Wq_hi[E_DIM * E_DIM];
__device__ __half g_Wq_lo[E_DIM * E_DIM];
__device__ __half g_Wk_hi[E_DIM * E_DIM];
__device__ __half g_Wk_lo[E_DIM * E_DIM];
__device__ __half g_Wv_hi[E_DIM * E_DIM];
__device__ __half g_Wv_lo[E_DIM * E_DIM];
__device__ __nv_bfloat16 g_Wo_hi[E_DIM * E_DIM];
__device__ __nv_bfloat16 g_Wo_lo[E_DIM * E_DIM];
__device__ float g_bq_eff[E_DIM];
__device__ float g_bk_eff[E_DIM];
__device__ float g_v   [TB * E_DIM];
__device__ float g_phiq[(size_t)TB * 2048];
__device__ float g_phik[(size_t)TB * 2048];
__device__ __nv_bfloat16 g_attn_hi[TB * E_DIM];
__device__ __nv_bfloat16 g_attn_lo[TB * E_DIM];

// ----------------------------- PTX helpers ---------------------------------
__device__ __forceinline__ uint32_t smem_to_u32(const void* p) {
    uint32_t a;
    asm("{ .reg .u64 t; cvta.to.shared.u64 t, %1; cvt.u32.u64 %0, t; }" : "=r"(a) : "l"(p));
    return a;
}
__device__ __forceinline__ void cp16(uint32_t dst, const void* src) {
    asm volatile("cp.async.cg.shared.global [%0], [%1], 16;" :: "r"(dst), "l"(src) : "memory");
}
#define CP_COMMIT() asm volatile("cp.async.commit_group;" ::: "memory")
#define CP_WAIT2()  asm volatile("cp.async.wait_group 2;" ::: "memory")

__device__ __forceinline__ void ldsm4(uint32_t* r, uint32_t addr) {
    asm volatile("ldmatrix.sync.aligned.m8n8.x4.shared.b16 {%0,%1,%2,%3}, [%4];"
                 : "=r"(r[0]), "=r"(r[1]), "=r"(r[2]), "=r"(r[3]) : "r"(addr));
}
// accumulate variants (d == c)
__device__ __forceinline__ void mma_f16(float* d, const uint32_t* a, const uint32_t* b) {
    asm volatile(
        "mma.sync.aligned.m16n8k16.row.col.f32.f16.f16.f32 "
        "{%0,%1,%2,%3}, {%4,%5,%6,%7}, {%8,%9}, {%0,%1,%2,%3};"
        : "+f"(d[0]), "+f"(d[1]), "+f"(d[2]), "+f"(d[3])
        : "r"(a[0]), "r"(a[1]), "r"(a[2]), "r"(a[3]), "r"(b[0]), "r"(b[1]));
}
__device__ __forceinline__ void mma_bf16(float* d, const uint32_t* a, const uint32_t* b) {
    asm volatile(
        "mma.sync.aligned.m16n8k16.row.col.f32.bf16.bf16.f32 "
        "{%0,%1,%2,%3}, {%4,%5,%6,%7}, {%8,%9}, {%0,%1,%2,%3};"
        : "+f"(d[0]), "+f"(d[1]), "+f"(d[2]), "+f"(d[3])
        : "r"(a[0]), "r"(a[1]), "r"(a[2]), "r"(a[3]), "r"(b[0]), "r"(b[1]));
}
// zero-C variants (d written fresh, c = 0) — first MMA of each drain group
__device__ __forceinline__ void mma_f16_zc(float* d, const uint32_t* a, const uint32_t* b) {
    asm volatile(
        "mma.sync.aligned.m16n8k16.row.col.f32.f16.f16.f32 "
        "{%0,%1,%2,%3}, {%4,%5,%6,%7}, {%8,%9}, {%10,%10,%10,%10};"
        : "=f"(d[0]), "=f"(d[1]), "=f"(d[2]), "=f"(d[3])
        : "r"(a[0]), "r"(a[1]), "r"(a[2]), "r"(a[3]), "r"(b[0]), "r"(b[1]),
          "f"(0.0f));
}
__device__ __forceinline__ void mma_bf16_zc(float* d, const uint32_t* a, const uint32_t* b) {
    asm volatile(
        "mma.sync.aligned.m16n8k16.row.col.f32.bf16.bf16.f32 "
        "{%0,%1,%2,%3}, {%4,%5,%6,%7}, {%8,%9}, {%10,%10,%10,%10};"
        : "=f"(d[0]), "=f"(d[1]), "=f"(d[2]), "=f"(d[3])
        : "r"(a[0]), "r"(a[1]), "r"(a[2]), "r"(a[3]), "r"(b[0]), "r"(b[1]),
          "f"(0.0f));
}

// ---------------------------------------------------------------------------
// fp32 -> fp16 hi/lo split (with pre-scale)
// ---------------------------------------------------------------------------
__global__ void __launch_bounds__(256) f32_to_f16hl(
    const float* __restrict__ in, __half* __restrict__ hi,
    __half* __restrict__ lo, int n, float scale)
{
    int i = (blockIdx.x * 256 + threadIdx.x) * 4;
    if (i >= n) return;
    float4 v = *(const float4*)(in + i);
    float a[4] = {v.x * scale, v.y * scale, v.z * scale, v.w * scale};
    __half h[4], l[4];
#pragma unroll
    for (int j = 0; j < 4; j++) {
        h[j] = __float2half_rn(a[j]);
        l[j] = __float2half_rn(a[j] - __half2float(h[j]));
    }
    *(__half2*)(hi + i)     = __halves2half2(h[0], h[1]);
    *(__half2*)(hi + i + 2) = __halves2half2(h[2], h[3]);
    *(__half2*)(lo + i)     = __halves2half2(l[0], l[1]);
    *(__half2*)(lo + i + 2) = __halves2half2(l[2], l[3]);
}

// fp32 -> bf16 hi/lo split
__global__ void __launch_bounds__(256) f32_to_bf16hl(
    const float* __restrict__ in, __nv_bfloat16* __restrict__ hi,
    __nv_bfloat16* __restrict__ lo, int n)
{
    int i = (blockIdx.x * 256 + threadIdx.x) * 4;
    if (i >= n) return;
    float4 v = *(const float4*)(in + i);
    float a[4] = {v.x, v.y, v.z, v.w};
    __nv_bfloat16 h[4], l[4];
#pragma unroll
    for (int j = 0; j < 4; j++) {
        h[j] = __float2bfloat16(a[j]);
        l[j] = __float2bfloat16(a[j] - __bfloat162float(h[j]));
    }
    *(__nv_bfloat162*)(hi + i)     = __halves2bfloat162(h[0], h[1]);
    *(__nv_bfloat162*)(hi + i + 2) = __halves2bfloat162(h[2], h[3]);
    *(__nv_bfloat162*)(lo + i)     = __halves2bfloat162(l[0], l[1]);
    *(__nv_bfloat162*)(lo + i + 2) = __halves2bfloat162(l[2], l[3]);
}

// ---------------------------------------------------------------------------
// Weight prep: Weff[h*64+k, e] = scale * sum_d rm[h,k,d] * W[h*64+d, e]
// matrix written as fp16 hi/lo with extra x64; beff fp32 (logical scale).
// ---------------------------------------------------------------------------
__global__ void __launch_bounds__(256) prep_weff(
    const float* __restrict__ rm, const float* __restrict__ W,
    const float* __restrict__ bvec, __half* __restrict__ Whi,
    __half* __restrict__ Wlo, float* __restrict__ beff, float scale)
{
    const int h  = blockIdx.y;
    const int e0 = blockIdx.x * 64;
    const int tid = threadIdx.x;

    __shared__ float rs[64][65];
    __shared__ float ws[64][65];

    for (int i = tid; i < 4096; i += 256) {
        int k = i >> 6, dd = i & 63;
        rs[k][dd] = rm[h * 4096 + i];
    }
    for (int i = tid; i < 4096; i += 256) {
        int dd = i >> 6, e = i & 63;
        ws[dd][e] = W[(size_t)(h * 64 + dd) * E_DIM + e0 + e];
    }
    __syncthreads();

    const int tk = (tid >> 4) * 4;
    const int te = (tid & 15) * 4;
    float acc[4][4];
#pragma unroll
    for (int i = 0; i < 4; i++)
#pragma unroll
        for (int j = 0; j < 4; j++) acc[i][j] = 0.f;

#pragma unroll 8
    for (int dd = 0; dd < 64; dd++) {
        float a0 = rs[tk + 0][dd], a1 = rs[tk + 1][dd];
        float a2 = rs[tk + 2][dd], a3 = rs[tk + 3][dd];
        float b0 = ws[dd][te + 0], b1 = ws[dd][te + 1];
        float b2 = ws[dd][te + 2], b3 = ws[dd][te + 3];
        acc[0][0] += a0 * b0; acc[0][1] += a0 * b1; acc[0][2] += a0 * b2; acc[0][3] += a0 * b3;
        acc[1][0] += a1 * b0; acc[1][1] += a1 * b1; acc[1][2] += a1 * b2; acc[1][3] += a1 * b3;
        acc[2][0] += a2 * b0; acc[2][1] += a2 * b1; acc[2][2] += a2 * b2; acc[2][3] += a2 * b3;
        acc[3][0] += a3 * b0; acc[3][1] += a3 * b1; acc[3][2] += a3 * b2; acc[3][3] += a3 * b3;
    }
#pragma unroll
    for (int i = 0; i < 4; i++)
#pragma unroll
        for (int j = 0; j < 4; j++) {
            float val = 64.f * scale * acc[i][j];
            size_t idx = (size_t)(h * 64 + tk + i) * E_DIM + e0 + te + j;
            __half hv = __float2half_rn(val);
            Whi[idx] = hv;
            Wlo[idx] = __float2half_rn(val - __half2float(hv));
        }

    if (blockIdx.x == 0 && tid < 64) {
        float s = 0.f;
        for (int dd = 0; dd < 64; dd++) s += rs[tid][dd] * bvec[h * 64 + dd];
        beff[h * 64 + tid] = scale * s;
    }
}

// ---------------------------------------------------------------------------
// one k-stage loader — 256 threads, 2 iterations (8 cp.async per thread)
// ---------------------------------------------------------------------------
template <typename ET>
__device__ __forceinline__ void load_stage(
    const ET* __restrict__ Ahi, const ET* __restrict__ Alo,
    const ET* __restrict__ Bhi, const ET* __restrict__ Blo,
    int m0, int n0, int kc0, uint32_t st, int tid)
{
#pragma unroll
    for (int i = 0; i < 2; i++) {
        const int idx = tid + 256 * i;
        const int row = idx >> 2;
        const int u = idx & 3;
        const uint32_t doff = row * ROW_B + u * 16;
        const size_t aoff = (size_t)(m0 + row) * E_DIM + kc0 + u * 8;
        const size_t boff = (size_t)(n0 + row) * E_DIM + kc0 + u * 8;
        cp16(st + doff,             Ahi + aoff);
        cp16(st + ARR_B + doff,     Alo + aoff);
        cp16(st + 2 * ARR_B + doff, Bhi + boff);
        cp16(st + 3 * ARR_B + doff, Blo + boff);
    }
}

// ---------------------------------------------------------------------------
// HMMA GEMM: C = escale * (A @ B^T) + bias, 3-term split.
// 256 threads, 8 warps, warp tile 32x64; zero-C drain-group starts;
// RN drain every chunk (MODE 1, amplified path) or every 2 chunks (MODE 0);
// 4-stage cp.async ring, prefetch distance 3, single sync per k-iter.
// MODE 0: C fp32, row stride 1024.   MODE 1: phi epilogue, row stride 2048.
// ---------------------------------------------------------------------------
template <int MODE, typename ET>
__global__ void __launch_bounds__(256, 1) tc_gemm(
    const ET* __restrict__ Ahi, const ET* __restrict__ Alo,
    const ET* __restrict__ Bhi, const ET* __restrict__ Blo,
    const float* __restrict__ bias, float* __restrict__ Cout, float escale)
{
    extern __shared__ char smem[];
    const uint32_t sbase = smem_to_u32(smem);
    const int tid = threadIdx.x;
    const int wid = tid >> 5;
    const int lane = tid & 31;
    const int m0 = blockIdx.y * BM;
    const int n0 = blockIdx.x * BN;

    float* bias_s = (float*)(smem + SM_BIAS);
    if (tid < 128) bias_s[tid] = bias[n0 + tid];

    const int wm = wid >> 1;     // 0..3 -> rows wm*32
    const int wn = wid & 1;      // 0..1 -> cols wn*64
    const int g = lane >> 3;
    const int r = lane & 7;

    // preload 3 of 4 stages
#pragma unroll
    for (int s = 0; s < 3; s++) {
        load_stage(Ahi, Alo, Bhi, Blo, m0, n0, s * BK,
                   sbase + SM_STAGE0 + s * STAGE_B, tid);
        CP_COMMIT();
    }

    float accm[2][8][4];
    float accw[2][8][4];
#pragma unroll
    for (int mt = 0; mt < 2; mt++)
#pragma unroll
        for (int j = 0; j < 8; j++)
#pragma unroll
            for (int c = 0; c < 4; c++) accm[mt][j][c] = 0.f;

    const uint32_t a_row_off = (uint32_t)((wm * 32 + (g & 1) * 8 + r) * ROW_B + (g >> 1) * 16);
    const uint32_t b_row_off = (uint32_t)((wn * 64 + (g >> 1) * 8 + r) * ROW_B + (g & 1) * 16);

#pragma unroll 1
    for (int kt = 0; kt < NKT; kt++) {
        CP_WAIT2();        // slot kt%4 ready
        __syncthreads();   // all warps done reading slot (kt+3)%4

        // refill slot (kt+3)%4 — 3 iterations ahead
        if (kt + 3 < NKT)
            load_stage(Ahi, Alo, Bhi, Blo, m0, n0, (kt + 3) * BK,
                       sbase + SM_STAGE0 + ((kt + 3) % NSTAGE) * STAGE_B, tid);
        CP_COMMIT();

        const uint32_t st = sbase + SM_STAGE0 + (kt % NSTAGE) * STAGE_B;
        const uint32_t sA[2] = { st, st + ARR_B };
        const uint32_t sB[2] = { st + 2 * ARR_B, st + 3 * ARR_B };
        // MODE 1 (amplified phi path): fresh accumulator every chunk (chain 6)
        // MODE 0 (unamplified): fresh every 2 chunks (chain 12)
        const bool fresh = (MODE == 1) || ((kt & 1) == 0);
        const bool drain = (MODE == 1) || ((kt & 1) == 1);

#pragma unroll
        for (int ks = 0; ks < 2; ks++) {
            uint32_t afr[2][2][4];   // [mt][hl][4]
            uint32_t bfr[4][2][4];   // [jp][hl][4]
#pragma unroll
            for (int mt = 0; mt < 2; mt++)
#pragma unroll
                for (int hl = 0; hl < 2; hl++)
                    ldsm4(afr[mt][hl], sA[hl] + a_row_off + mt * (16 * ROW_B) + ks * 32);
#pragma unroll
            for (int jp = 0; jp < 4; jp++)
#pragma unroll
                for (int hl = 0; hl < 2; hl++)
                    ldsm4(bfr[jp][hl], sB[hl] + b_row_off + jp * (16 * ROW_B) + ks * 32);

#pragma unroll
            for (int t = 0; t < 3; t++) {
                const int pa = (t == 2) ? 1 : 0;   // hh, hl, lh
                const int pb = (t == 1) ? 1 : 0;
                const bool zc = fresh && ks == 0 && t == 0;
#pragma unroll
                for (int mt = 0; mt < 2; mt++)
#pragma unroll
                    for (int j = 0; j < 8; j++) {
                        const uint32_t* bj = &bfr[j >> 1][pb][(j & 1) * 2];
                        if (std::is_same<ET, __half>::value) {
                            if (zc) mma_f16_zc(accw[mt][j], afr[mt][pa], bj);
                            else    mma_f16(accw[mt][j], afr[mt][pa], bj);
                        } else {
                            if (zc) mma_bf16_zc(accw[mt][j], afr[mt][pa], bj);
                            else    mma_bf16(accw[mt][j], afr[mt][pa], bj);
                        }
                    }
            }
        }
        if (drain) {   // working -> master (IEEE-RN)
#pragma unroll
            for (int mt = 0; mt < 2; mt++)
#pragma unroll
                for (int j = 0; j < 8; j++)
#pragma unroll
                    for (int c = 0; c < 4; c++) accm[mt][j][c] += accw[mt][j][c];
        }
    }

    // ------------------------------ epilogue --------------------------------
    const int qr = lane >> 2;
    const int qc = (lane & 3) * 2;
#pragma unroll
    for (int mt = 0; mt < 2; mt++) {
        const int row0 = m0 + wm * 32 + mt * 16 + qr;
#pragma unroll
        for (int j = 0; j < 8; j++) {
            const int coll = wn * 64 + j * 8 + qc;
            const int col = n0 + coll;
            const float b0 = bias_s[coll], b1 = bias_s[coll + 1];
            if (MODE == 0) {
                float2 v0 = make_float2(accm[mt][j][0] * escale + b0,
                                        accm[mt][j][1] * escale + b1);
                float2 v1 = make_float2(accm[mt][j][2] * escale + b0,
                                        accm[mt][j][3] * escale + b1);
                *(float2*)(Cout + (size_t)row0 * E_DIM + col) = v0;
                *(float2*)(Cout + (size_t)(row0 + 8) * E_DIM + col) = v1;
            } else {
                const int h = col >> 6, k = col & 63;
                float s0, c0s, s1, c1s, s2, c2s, s3, c3s;
                __sincosf(accm[mt][j][0] * escale + b0, &s0, &c0s);
                __sincosf(accm[mt][j][1] * escale + b1, &s1, &c1s);
                __sincosf(accm[mt][j][2] * escale + b0, &s2, &c2s);
                __sincosf(accm[mt][j][3] * escale + b1, &s3, &c3s);
                float* p0 = Cout + (size_t)row0 * 2048 + h * 128 + k;
                float* p1 = Cout + (size_t)(row0 + 8) * 2048 + h * 128 + k;
                p0[0] = s0 * 0.125f; p0[1]  = s1 * 0.125f;
                p0[64] = c0s * 0.125f; p0[65] = c1s * 0.125f;
                p1[0] = s2 * 0.125f; p1[1]  = s3 * 0.125f;
                p1[64] = c2s * 0.125f; p1[65] = c3s * 0.125f;
            }
        }
    }
}

// ---------------------------------------------------------------------------
// Causal RFA scan, d-split x2, TWO timesteps per iteration.
// block bx = bh*2 + dh handles output dims d in [dh*32, dh*32+32).
// 256 threads: dl = tid&31, kg = tid>>5. Thread owns s[kg*16+j][dh*32+dl].
// R6-proven 2-sync skeleton, amortized over 2 steps. attn -> bf16 hi/lo.
// ---------------------------------------------------------------------------
__global__ void __launch_bounds__(256) rfa_scan(
    const float* __restrict__ phiq, const float* __restrict__ phik,
    const float* __restrict__ v, __nv_bfloat16* __restrict__ attn_hi,
    __nv_bfloat16* __restrict__ attn_lo)
{
    const int bx = blockIdx.x;       // bh*2 + dh
    const int dh = bx & 1;
    const int bh = bx >> 1;
    const int h = bh & 15;
    const int b = bh >> 4;
    const int tid = threadIdx.x;
    const int dl = tid & 31;
    const int kg = tid >> 5;         // 0..7

    __shared__ float s_pq[2][2][128], s_pk[2][2][128], s_v[2][2][32];
    __shared__ float s_z[128];
    __shared__ float s_red[2][256];   // [step][tid]
    __shared__ float s_qzp[2][4];     // [step][warp128]

    float s_loc[16];
#pragma unroll
    for (int j = 0; j < 16; j++) s_loc[j] = 0.f;
    if (tid < 128) s_z[tid] = 0.f;

    const size_t phi_stride = (size_t)B_DIM * 2048;
    const size_t v_stride   = (size_t)B_DIM * 1024;
    const float* pq_base = phiq + (size_t)b * 2048 + h * 128;
    const float* pk_base = phik + (size_t)b * 2048 + h * 128;
    const float* v_base  = v    + (size_t)b * 1024 + h * 64 + dh * 32;
    const size_t o_off   = (size_t)b * 1024 + h * 64 + dh * 32;

    // preload pair 0 (t = 0, 1)
    float ld_pq0 = 0.f, ld_pq1 = 0.f, ld_pk0 = 0.f, ld_pk1 = 0.f;
    float ld_v0 = 0.f, ld_v1 = 0.f;
    if (tid < 128) {
        ld_pq0 = pq_base[tid];              ld_pk0 = pk_base[tid];
        ld_pq1 = pq_base[phi_stride + tid]; ld_pk1 = pk_base[phi_stride + tid];
    }
    if (tid < 32) { ld_v0 = v_base[tid]; ld_v1 = v_base[v_stride + tid]; }
    int buf = 0;
    if (tid < 128) {
        s_pq[0][0][tid] = ld_pq0; s_pk[0][0][tid] = ld_pk0;
        s_pq[0][1][tid] = ld_pq1; s_pk[0][1][tid] = ld_pk1;
    }
    if (tid < 32) { s_v[0][0][tid] = ld_v0; s_v[0][1][tid] = ld_v1; }
    __syncthreads();

    const int NPAIR = T_DIM / 2;   // 1024
    for (int it = 0; it < NPAIR; it++) {
        const size_t t0 = (size_t)(2 * it);

        // prefetch pair it+1 (gmem -> regs)
        if (it + 1 < NPAIR) {
            if (tid < 128) {
                ld_pq0 = pq_base[(t0 + 2) * phi_stride + tid];
                ld_pk0 = pk_base[(t0 + 2) * phi_stride + tid];
                ld_pq1 = pq_base[(t0 + 3) * phi_stride + tid];
                ld_pk1 = pk_base[(t0 + 3) * phi_stride + tid];
            }
            if (tid < 32) {
                ld_v0 = v_base[(t0 + 2) * v_stride + tid];
                ld_v1 = v_base[(t0 + 3) * v_stride + tid];
            }
        }

        // s updates + q.s partials for both steps (sequential in s, paired)
        const float vd0 = s_v[buf][0][dl];
        const float vd1 = s_v[buf][1][dl];
        const float* pk0 = &s_pk[buf][0][kg * 16];
        const float* pk1 = &s_pk[buf][1][kg * 16];
        const float* pq0 = &s_pq[buf][0][kg * 16];
        const float* pq1 = &s_pq[buf][1][kg * 16];
        float a0x = 0.f, a0y = 0.f, a0z = 0.f, a0w = 0.f;
        float a1x = 0.f, a1y = 0.f, a1z = 0.f, a1w = 0.f;
#pragma unroll
        for (int j = 0; j < 16; j += 4) {
            float4 k0 = *(const float4*)(pk0 + j);
            float4 q0 = *(const float4*)(pq0 + j);
            float4 k1 = *(const float4*)(pk1 + j);
            float4 q1 = *(const float4*)(pq1 + j);
            s_loc[j + 0] += k0.x * vd0; a0x += q0.x * s_loc[j + 0];
            s_loc[j + 0] += k1.x * vd1; a1x += q1.x * s_loc[j + 0];
            s_loc[j + 1] += k0.y * vd0; a0y += q0.y * s_loc[j + 1];
            s_loc[j + 1] += k1.y * vd1; a1y += q1.y * s_loc[j + 1];
            s_loc[j + 2] += k0.z * vd0; a0z += q0.z * s_loc[j + 2];
            s_loc[j + 2] += k1.z * vd1; a1z += q1.z * s_loc[j + 2];
            s_loc[j + 3] += k0.w * vd0; a0w += q0.w * s_loc[j + 3];
            s_loc[j + 3] += k1.w * vd1; a1w += q1.w * s_loc[j + 3];
        }
        s_red[0][tid] = (a0x + a0y) + (a0z + a0w);
        s_red[1][tid] = (a1x + a1y) + (a1z + a1w);

        // z updates + qz partials for both steps (threads 0..127, one per k)
        float qzp0 = 0.f, qzp1 = 0.f;
        if (tid < 128) {
            float z1 = s_z[tid] + s_pk[buf][0][tid];
            qzp0 = s_pq[buf][0][tid] * z1;
            float z2 = z1 + s_pk[buf][1][tid];
            qzp1 = s_pq[buf][1][tid] * z2;
            s_z[tid] = z2;
        }
#pragma unroll
        for (int off = 16; off; off >>= 1) {
            qzp0 += __shfl_xor_sync(0xffffffffu, qzp0, off);
            qzp1 += __shfl_xor_sync(0xffffffffu, qzp1, off);
        }
        if (tid < 128 && (tid & 31) == 0) {
            s_qzp[0][tid >> 5] = qzp0;
            s_qzp[1][tid >> 5] = qzp1;
        }
        __syncthreads();

        // finalize + write attn[t0], attn[t0+1] for this block's 32 d's
        if (tid < 32) {
#pragma unroll
            for (int stp = 0; stp < 2; stp++) {
                const float* rd = s_red[stp];
                float qs = ((rd[dl] + rd[32 + dl]) + (rd[64 + dl] + rd[96 + dl])) +
                           ((rd[128 + dl] + rd[160 + dl]) + (rd[192 + dl] + rd[224 + dl]));
                float qz = (s_qzp[stp][0] + s_qzp[stp][1]) +
                           (s_qzp[stp][2] + s_qzp[stp][3]);
                qz = fmaxf(qz, EPS_RFA);
                float o = qs / qz;
                __nv_bfloat16 hv = __float2bfloat16(o);
                size_t idx = (t0 + stp) * v_stride + o_off + dl;
                attn_hi[idx] = hv;
                attn_lo[idx] = __float2bfloat16(o - __bfloat162float(hv));
            }
        }

        // stage prefetched pair into the other buffer
        buf ^= 1;
        if (it + 1 < NPAIR) {
            if (tid < 128) {
                s_pq[buf][0][tid] = ld_pq0; s_pk[buf][0][tid] = ld_pk0;
                s_pq[buf][1][tid] = ld_pq1; s_pk[buf][1][tid] = ld_pk1;
            }
            if (tid < 32) { s_v[buf][0][tid] = ld_v0; s_v[buf][1][tid] = ld_v1; }
        }
        __syncthreads();
    }
}

// ---------------------------------------------------------------------------
extern "C" void kernel_launch(void* const* d_in, const int* in_sizes, int n_in,
                              void* d_out, int out_size)
{
    const float* x  = (const float*)d_in[0];
    const float* rm = (const float*)d_in[1];
    const float* Wq = (const float*)d_in[2];
    const float* bq = (const float*)d_in[3];
    const float* Wk = (const float*)d_in[4];
    const float* bk = (const float*)d_in[5];
    const float* Wv = (const float*)d_in[6];
    const float* bv = (const float*)d_in[7];
    const float* Wo = (const float*)d_in[8];
    const float* bo = (const float*)d_in[9];
    float* out = (float*)d_out;

    __half *x_hi, *x_lo, *Wq_hi, *Wq_lo, *Wk_hi, *Wk_lo, *Wv_hi, *Wv_lo;
    __nv_bfloat16 *Wo_hi, *Wo_lo, *attn_hi, *attn_lo;
    float *bq_eff, *bk_eff, *vbuf, *phiq, *phik;
    cudaGetSymbolAddress((void**)&x_hi, g_x_hi);
    cudaGetSymbolAddress((void**)&x_lo, g_x_lo);
    cudaGetSymbolAddress((void**)&Wq_hi, g_Wq_hi);
    cudaGetSymbolAddress((void**)&Wq_lo, g_Wq_lo);
    cudaGetSymbolAddress((void**)&Wk_hi, g_Wk_hi);
    cudaGetSymbolAddress((void**)&Wk_lo, g_Wk_lo);
    cudaGetSymbolAddress((void**)&Wv_hi, g_Wv_hi);
    cudaGetSymbolAddress((void**)&Wv_lo, g_Wv_lo);
    cudaGetSymbolAddress((void**)&Wo_hi, g_Wo_hi);
    cudaGetSymbolAddress((void**)&Wo_lo, g_Wo_lo);
    cudaGetSymbolAddress((void**)&attn_hi, g_attn_hi);
    cudaGetSymbolAddress((void**)&attn_lo, g_attn_lo);
    cudaGetSymbolAddress((void**)&bq_eff, g_bq_eff);
    cudaGetSymbolAddress((void**)&bk_eff, g_bk_eff);
    cudaGetSymbolAddress((void**)&vbuf, g_v);
    cudaGetSymbolAddress((void**)&phiq, g_phiq);
    cudaGetSymbolAddress((void**)&phik, g_phik);

    cudaFuncSetAttribute((const void*)tc_gemm<0, __half>,
                         cudaFuncAttributeMaxDynamicSharedMemorySize, SM_TOTAL);
    cudaFuncSetAttribute((const void*)tc_gemm<1, __half>,
                         cudaFuncAttributeMaxDynamicSharedMemorySize, SM_TOTAL);
    cudaFuncSetAttribute((const void*)tc_gemm<0, __nv_bfloat16>,
                         cudaFuncAttributeMaxDynamicSharedMemorySize, SM_TOTAL);

    // conversions + weight prep: x scaled x256 (fp16 lo stays normal),
    // fp16 weights x64; bf16 Wo unscaled.
    f32_to_f16hl<<<TB * E_DIM / 1024, 256>>>(x, x_hi, x_lo, TB * E_DIM, 256.0f);
    prep_weff<<<dim3(16, 16), 256>>>(rm, Wq, bq, Wq_hi, Wq_lo, bq_eff, 0.125f);
    prep_weff<<<dim3(16, 16), 256>>>(rm, Wk, bk, Wk_hi, Wk_lo, bk_eff, 1.0f);
    f32_to_f16hl<<<E_DIM * E_DIM / 1024, 256>>>(Wv, Wv_hi, Wv_lo, E_DIM * E_DIM, 64.0f);
    f32_to_bf16hl<<<E_DIM * E_DIM / 1024, 256>>>(Wo, Wo_hi, Wo_lo, E_DIM * E_DIM);

    // tensor-core GEMMs (escale undoes x256 * x64)
    dim3 gg(E_DIM / BN, TB / BM);   // (8, 128)
    const float inv = 1.0f / 16384.0f;
    tc_gemm<1, __half><<<gg, 256, SM_TOTAL>>>(x_hi, x_lo, Wq_hi, Wq_lo, bq_eff, phiq, inv);
    tc_gemm<1, __half><<<gg, 256, SM_TOTAL>>>(x_hi, x_lo, Wk_hi, Wk_lo, bk_eff, phik, inv);
    tc_gemm<0, __half><<<gg, 256, SM_TOTAL>>>(x_hi, x_lo, Wv_hi, Wv_lo, bv, vbuf, inv);

    // causal scan, d-split x2, 2 timesteps/iter (256 blocks; attn bf16 split)
    rfa_scan<<<B_DIM * H_DIM * 2, 256>>>(phiq, phik, vbuf, attn_hi, attn_lo);

    // output projection (bf16 split, unamplified error path)
    tc_gemm<0, __nv_bfloat16><<<gg, 256, SM_TOTAL>>>(attn_hi, attn_lo, Wo_hi, Wo_lo, bo, out, 1.0f);
}

// round 12
// speedup vs baseline: 1.3575x; 1.0647x over previous
#include <cuda_runtime.h>
#include <cuda_fp16.h>
#include <cuda_bf16.h>
#include <cstdint>
#include <type_traits>

// ---------------------------------------------------------------------------
// CausalAttention (random-feature attention) — mma.sync 3-term split GEMMs
// (zero-C chunk starts, RN drain: every chunk on phi GEMMs, every 2 on v/out)
// + d-split x2, 4-timesteps-per-iteration causal scan (R6 2-sync skeleton).
// ---------------------------------------------------------------------------

#define T_DIM 2048
#define B_DIM 8
#define E_DIM 1024
#define H_DIM 16
#define TB    (T_DIM * B_DIM)          // 16384 rows
#define EPS_RFA 1e-6f

#define BM 128
#define BN 128
#define BK 32
#define NKT (E_DIM / BK)                // 32
#define ROW_B 80
#define ARR_B (128 * ROW_B)
#define STAGE_B (4 * ARR_B)             // 40960
#define NSTAGE 4
#define SM_BIAS 0
#define SM_STAGE0 1024
#define SM_TOTAL (SM_STAGE0 + NSTAGE * STAGE_B)   // 164864

// ------------------------- scratch (static device) -------------------------
__device__ __half g_x_hi[TB * E_DIM];
__device__ __half g_x_lo[TB * E_DIM];
__device__ __half g_Wq_hi[E_DIM * E_DIM];
__device__ __half g_Wq_lo[E_DIM * E_DIM];
__device__ __half g_Wk_hi[E_DIM * E_DIM];
__device__ __half g_Wk_lo[E_DIM * E_DIM];
__device__ __half g_Wv_hi[E_DIM * E_DIM];
__device__ __half g_Wv_lo[E_DIM * E_DIM];
__device__ __nv_bfloat16 g_Wo_hi[E_DIM * E_DIM];
__device__ __nv_bfloat16 g_Wo_lo[E_DIM * E_DIM];
__device__ float g_bq_eff[E_DIM];
__device__ float g_bk_eff[E_DIM];
__device__ float g_v   [TB * E_DIM];
__device__ float g_phiq[(size_t)TB * 2048];
__device__ float g_phik[(size_t)TB * 2048];
__device__ __nv_bfloat16 g_attn_hi[TB * E_DIM];
__device__ __nv_bfloat16 g_attn_lo[TB * E_DIM];

// ----------------------------- PTX helpers ---------------------------------
__device__ __forceinline__ uint32_t smem_to_u32(const void* p) {
    uint32_t a;
    asm("{ .reg .u64 t; cvta.to.shared.u64 t, %1; cvt.u32.u64 %0, t; }" : "=r"(a) : "l"(p));
    return a;
}
__device__ __forceinline__ void cp16(uint32_t dst, const void* src) {
    asm volatile("cp.async.cg.shared.global [%0], [%1], 16;" :: "r"(dst), "l"(src) : "memory");
}
#define CP_COMMIT() asm volatile("cp.async.commit_group;" ::: "memory")
#define CP_WAIT2()  asm volatile("cp.async.wait_group 2;" ::: "memory")

__device__ __forceinline__ void ldsm4(uint32_t* r, uint32_t addr) {
    asm volatile("ldmatrix.sync.aligned.m8n8.x4.shared.b16 {%0,%1,%2,%3}, [%4];"
                 : "=r"(r[0]), "=r"(r[1]), "=r"(r[2]), "=r"(r[3]) : "r"(addr));
}
// accumulate variants (d == c)
__device__ __forceinline__ void mma_f16(float* d, const uint32_t* a, const uint32_t* b) {
    asm volatile(
        "mma.sync.aligned.m16n8k16.row.col.f32.f16.f16.f32 "
        "{%0,%1,%2,%3}, {%4,%5,%6,%7}, {%8,%9}, {%0,%1,%2,%3};"
        : "+f"(d[0]), "+f"(d[1]), "+f"(d[2]), "+f"(d[3])
        : "r"(a[0]), "r"(a[1]), "r"(a[2]), "r"(a[3]), "r"(b[0]), "r"(b[1]));
}
__device__ __forceinline__ void mma_bf16(float* d, const uint32_t* a, const uint32_t* b) {
    asm volatile(
        "mma.sync.aligned.m16n8k16.row.col.f32.bf16.bf16.f32 "
        "{%0,%1,%2,%3}, {%4,%5,%6,%7}, {%8,%9}, {%0,%1,%2,%3};"
        : "+f"(d[0]), "+f"(d[1]), "+f"(d[2]), "+f"(d[3])
        : "r"(a[0]), "r"(a[1]), "r"(a[2]), "r"(a[3]), "r"(b[0]), "r"(b[1]));
}
// zero-C variants (d written fresh, c = 0) — first MMA of each drain group
__device__ __forceinline__ void mma_f16_zc(float* d, const uint32_t* a, const uint32_t* b) {
    asm volatile(
        "mma.sync.aligned.m16n8k16.row.col.f32.f16.f16.f32 "
        "{%0,%1,%2,%3}, {%4,%5,%6,%7}, {%8,%9}, {%10,%10,%10,%10};"
        : "=f"(d[0]), "=f"(d[1]), "=f"(d[2]), "=f"(d[3])
        : "r"(a[0]), "r"(a[1]), "r"(a[2]), "r"(a[3]), "r"(b[0]), "r"(b[1]),
          "f"(0.0f));
}
__device__ __forceinline__ void mma_bf16_zc(float* d, const uint32_t* a, const uint32_t* b) {
    asm volatile(
        "mma.sync.aligned.m16n8k16.row.col.f32.bf16.bf16.f32 "
        "{%0,%1,%2,%3}, {%4,%5,%6,%7}, {%8,%9}, {%10,%10,%10,%10};"
        : "=f"(d[0]), "=f"(d[1]), "=f"(d[2]), "=f"(d[3])
        : "r"(a[0]), "r"(a[1]), "r"(a[2]), "r"(a[3]), "r"(b[0]), "r"(b[1]),
          "f"(0.0f));
}

// ---------------------------------------------------------------------------
// fp32 -> fp16 hi/lo split (with pre-scale)
// ---------------------------------------------------------------------------
__global__ void __launch_bounds__(256) f32_to_f16hl(
    const float* __restrict__ in, __half* __restrict__ hi,
    __half* __restrict__ lo, int n, float scale)
{
    int i = (blockIdx.x * 256 + threadIdx.x) * 4;
    if (i >= n) return;
    float4 v = *(const float4*)(in + i);
    float a[4] = {v.x * scale, v.y * scale, v.z * scale, v.w * scale};
    __half h[4], l[4];
#pragma unroll
    for (int j = 0; j < 4; j++) {
        h[j] = __float2half_rn(a[j]);
        l[j] = __float2half_rn(a[j] - __half2float(h[j]));
    }
    *(__half2*)(hi + i)     = __halves2half2(h[0], h[1]);
    *(__half2*)(hi + i + 2) = __halves2half2(h[2], h[3]);
    *(__half2*)(lo + i)     = __halves2half2(l[0], l[1]);
    *(__half2*)(lo + i + 2) = __halves2half2(l[2], l[3]);
}

// fp32 -> bf16 hi/lo split
__global__ void __launch_bounds__(256) f32_to_bf16hl(
    const float* __restrict__ in, __nv_bfloat16* __restrict__ hi,
    __nv_bfloat16* __restrict__ lo, int n)
{
    int i = (blockIdx.x * 256 + threadIdx.x) * 4;
    if (i >= n) return;
    float4 v = *(const float4*)(in + i);
    float a[4] = {v.x, v.y, v.z, v.w};
    __nv_bfloat16 h[4], l[4];
#pragma unroll
    for (int j = 0; j < 4; j++) {
        h[j] = __float2bfloat16(a[j]);
        l[j] = __float2bfloat16(a[j] - __bfloat162float(h[j]));
    }
    *(__nv_bfloat162*)(hi + i)     = __halves2bfloat162(h[0], h[1]);
    *(__nv_bfloat162*)(hi + i + 2) = __halves2bfloat162(h[2], h[3]);
    *(__nv_bfloat162*)(lo + i)     = __halves2bfloat162(l[0], l[1]);
    *(__nv_bfloat162*)(lo + i + 2) = __halves2bfloat162(l[2], l[3]);
}

// ---------------------------------------------------------------------------
// Weight prep: Weff[h*64+k, e] = scale * sum_d rm[h,k,d] * W[h*64+d, e]
// matrix written as fp16 hi/lo with extra x64; beff fp32 (logical scale).
// ---------------------------------------------------------------------------
__global__ void __launch_bounds__(256) prep_weff(
    const float* __restrict__ rm, const float* __restrict__ W,
    const float* __restrict__ bvec, __half* __restrict__ Whi,
    __half* __restrict__ Wlo, float* __restrict__ beff, float scale)
{
    const int h  = blockIdx.y;
    const int e0 = blockIdx.x * 64;
    const int tid = threadIdx.x;

    __shared__ float rs[64][65];
    __shared__ float ws[64][65];

    for (int i = tid; i < 4096; i += 256) {
        int k = i >> 6, dd = i & 63;
        rs[k][dd] = rm[h * 4096 + i];
    }
    for (int i = tid; i < 4096; i += 256) {
        int dd = i >> 6, e = i & 63;
        ws[dd][e] = W[(size_t)(h * 64 + dd) * E_DIM + e0 + e];
    }
    __syncthreads();

    const int tk = (tid >> 4) * 4;
    const int te = (tid & 15) * 4;
    float acc[4][4];
#pragma unroll
    for (int i = 0; i < 4; i++)
#pragma unroll
        for (int j = 0; j < 4; j++) acc[i][j] = 0.f;

#pragma unroll 8
    for (int dd = 0; dd < 64; dd++) {
        float a0 = rs[tk + 0][dd], a1 = rs[tk + 1][dd];
        float a2 = rs[tk + 2][dd], a3 = rs[tk + 3][dd];
        float b0 = ws[dd][te + 0], b1 = ws[dd][te + 1];
        float b2 = ws[dd][te + 2], b3 = ws[dd][te + 3];
        acc[0][0] += a0 * b0; acc[0][1] += a0 * b1; acc[0][2] += a0 * b2; acc[0][3] += a0 * b3;
        acc[1][0] += a1 * b0; acc[1][1] += a1 * b1; acc[1][2] += a1 * b2; acc[1][3] += a1 * b3;
        acc[2][0] += a2 * b0; acc[2][1] += a2 * b1; acc[2][2] += a2 * b2; acc[2][3] += a2 * b3;
        acc[3][0] += a3 * b0; acc[3][1] += a3 * b1; acc[3][2] += a3 * b2; acc[3][3] += a3 * b3;
    }
#pragma unroll
    for (int i = 0; i < 4; i++)
#pragma unroll
        for (int j = 0; j < 4; j++) {
            float val = 64.f * scale * acc[i][j];
            size_t idx = (size_t)(h * 64 + tk + i) * E_DIM + e0 + te + j;
            __half hv = __float2half_rn(val);
            Whi[idx] = hv;
            Wlo[idx] = __float2half_rn(val - __half2float(hv));
        }

    if (blockIdx.x == 0 && tid < 64) {
        float s = 0.f;
        for (int dd = 0; dd < 64; dd++) s += rs[tid][dd] * bvec[h * 64 + dd];
        beff[h * 64 + tid] = scale * s;
    }
}

// ---------------------------------------------------------------------------
// one k-stage loader — 256 threads, 2 iterations (8 cp.async per thread)
// ---------------------------------------------------------------------------
template <typename ET>
__device__ __forceinline__ void load_stage(
    const ET* __restrict__ Ahi, const ET* __restrict__ Alo,
    const ET* __restrict__ Bhi, const ET* __restrict__ Blo,
    int m0, int n0, int kc0, uint32_t st, int tid)
{
#pragma unroll
    for (int i = 0; i < 2; i++) {
        const int idx = tid + 256 * i;
        const int row = idx >> 2;
        const int u = idx & 3;
        const uint32_t doff = row * ROW_B + u * 16;
        const size_t aoff = (size_t)(m0 + row) * E_DIM + kc0 + u * 8;
        const size_t boff = (size_t)(n0 + row) * E_DIM + kc0 + u * 8;
        cp16(st + doff,             Ahi + aoff);
        cp16(st + ARR_B + doff,     Alo + aoff);
        cp16(st + 2 * ARR_B + doff, Bhi + boff);
        cp16(st + 3 * ARR_B + doff, Blo + boff);
    }
}

// ---------------------------------------------------------------------------
// HMMA GEMM: C = escale * (A @ B^T) + bias, 3-term split.
// 256 threads, 8 warps, warp tile 32x64; zero-C drain-group starts;
// RN drain every chunk (MODE 1, amplified path) or every 2 chunks (MODE 0);
// 4-stage cp.async ring, prefetch distance 3, single sync per k-iter.
// MODE 0: C fp32, row stride 1024.   MODE 1: phi epilogue, row stride 2048.
// ---------------------------------------------------------------------------
template <int MODE, typename ET>
__global__ void __launch_bounds__(256, 1) tc_gemm(
    const ET* __restrict__ Ahi, const ET* __restrict__ Alo,
    const ET* __restrict__ Bhi, const ET* __restrict__ Blo,
    const float* __restrict__ bias, float* __restrict__ Cout, float escale)
{
    extern __shared__ char smem[];
    const uint32_t sbase = smem_to_u32(smem);
    const int tid = threadIdx.x;
    const int wid = tid >> 5;
    const int lane = tid & 31;
    const int m0 = blockIdx.y * BM;
    const int n0 = blockIdx.x * BN;

    float* bias_s = (float*)(smem + SM_BIAS);
    if (tid < 128) bias_s[tid] = bias[n0 + tid];

    const int wm = wid >> 1;     // 0..3 -> rows wm*32
    const int wn = wid & 1;      // 0..1 -> cols wn*64
    const int g = lane >> 3;
    const int r = lane & 7;

    // preload 3 of 4 stages
#pragma unroll
    for (int s = 0; s < 3; s++) {
        load_stage(Ahi, Alo, Bhi, Blo, m0, n0, s * BK,
                   sbase + SM_STAGE0 + s * STAGE_B, tid);
        CP_COMMIT();
    }

    float accm[2][8][4];
    float accw[2][8][4];
#pragma unroll
    for (int mt = 0; mt < 2; mt++)
#pragma unroll
        for (int j = 0; j < 8; j++)
#pragma unroll
            for (int c = 0; c < 4; c++) accm[mt][j][c] = 0.f;

    const uint32_t a_row_off = (uint32_t)((wm * 32 + (g & 1) * 8 + r) * ROW_B + (g >> 1) * 16);
    const uint32_t b_row_off = (uint32_t)((wn * 64 + (g >> 1) * 8 + r) * ROW_B + (g & 1) * 16);

#pragma unroll 1
    for (int kt = 0; kt < NKT; kt++) {
        CP_WAIT2();        // slot kt%4 ready
        __syncthreads();   // all warps done reading slot (kt+3)%4

        // refill slot (kt+3)%4 — 3 iterations ahead
        if (kt + 3 < NKT)
            load_stage(Ahi, Alo, Bhi, Blo, m0, n0, (kt + 3) * BK,
                       sbase + SM_STAGE0 + ((kt + 3) % NSTAGE) * STAGE_B, tid);
        CP_COMMIT();

        const uint32_t st = sbase + SM_STAGE0 + (kt % NSTAGE) * STAGE_B;
        const uint32_t sA[2] = { st, st + ARR_B };
        const uint32_t sB[2] = { st + 2 * ARR_B, st + 3 * ARR_B };
        // MODE 1 (amplified phi path): fresh accumulator every chunk (chain 6)
        // MODE 0 (unamplified): fresh every 2 chunks (chain 12)
        const bool fresh = (MODE == 1) || ((kt & 1) == 0);
        const bool drain = (MODE == 1) || ((kt & 1) == 1);

#pragma unroll
        for (int ks = 0; ks < 2; ks++) {
            uint32_t afr[2][2][4];   // [mt][hl][4]
            uint32_t bfr[4][2][4];   // [jp][hl][4]
#pragma unroll
            for (int mt = 0; mt < 2; mt++)
#pragma unroll
                for (int hl = 0; hl < 2; hl++)
                    ldsm4(afr[mt][hl], sA[hl] + a_row_off + mt * (16 * ROW_B) + ks * 32);
#pragma unroll
            for (int jp = 0; jp < 4; jp++)
#pragma unroll
                for (int hl = 0; hl < 2; hl++)
                    ldsm4(bfr[jp][hl], sB[hl] + b_row_off + jp * (16 * ROW_B) + ks * 32);

#pragma unroll
            for (int t = 0; t < 3; t++) {
                const int pa = (t == 2) ? 1 : 0;   // hh, hl, lh
                const int pb = (t == 1) ? 1 : 0;
                const bool zc = fresh && ks == 0 && t == 0;
#pragma unroll
                for (int mt = 0; mt < 2; mt++)
#pragma unroll
                    for (int j = 0; j < 8; j++) {
                        const uint32_t* bj = &bfr[j >> 1][pb][(j & 1) * 2];
                        if (std::is_same<ET, __half>::value) {
                            if (zc) mma_f16_zc(accw[mt][j], afr[mt][pa], bj);
                            else    mma_f16(accw[mt][j], afr[mt][pa], bj);
                        } else {
                            if (zc) mma_bf16_zc(accw[mt][j], afr[mt][pa], bj);
                            else    mma_bf16(accw[mt][j], afr[mt][pa], bj);
                        }
                    }
            }
        }
        if (drain) {   // working -> master (IEEE-RN)
#pragma unroll
            for (int mt = 0; mt < 2; mt++)
#pragma unroll
                for (int j = 0; j < 8; j++)
#pragma unroll
                    for (int c = 0; c < 4; c++) accm[mt][j][c] += accw[mt][j][c];
        }
    }

    // ------------------------------ epilogue --------------------------------
    const int qr = lane >> 2;
    const int qc = (lane & 3) * 2;
#pragma unroll
    for (int mt = 0; mt < 2; mt++) {
        const int row0 = m0 + wm * 32 + mt * 16 + qr;
#pragma unroll
        for (int j = 0; j < 8; j++) {
            const int coll = wn * 64 + j * 8 + qc;
            const int col = n0 + coll;
            const float b0 = bias_s[coll], b1 = bias_s[coll + 1];
            if (MODE == 0) {
                float2 v0 = make_float2(accm[mt][j][0] * escale + b0,
                                        accm[mt][j][1] * escale + b1);
                float2 v1 = make_float2(accm[mt][j][2] * escale + b0,
                                        accm[mt][j][3] * escale + b1);
                *(float2*)(Cout + (size_t)row0 * E_DIM + col) = v0;
                *(float2*)(Cout + (size_t)(row0 + 8) * E_DIM + col) = v1;
            } else {
                const int h = col >> 6, k = col & 63;
                float s0, c0s, s1, c1s, s2, c2s, s3, c3s;
                __sincosf(accm[mt][j][0] * escale + b0, &s0, &c0s);
                __sincosf(accm[mt][j][1] * escale + b1, &s1, &c1s);
                __sincosf(accm[mt][j][2] * escale + b0, &s2, &c2s);
                __sincosf(accm[mt][j][3] * escale + b1, &s3, &c3s);
                float* p0 = Cout + (size_t)row0 * 2048 + h * 128 + k;
                float* p1 = Cout + (size_t)(row0 + 8) * 2048 + h * 128 + k;
                p0[0] = s0 * 0.125f; p0[1]  = s1 * 0.125f;
                p0[64] = c0s * 0.125f; p0[65] = c1s * 0.125f;
                p1[0] = s2 * 0.125f; p1[1]  = s3 * 0.125f;
                p1[64] = c2s * 0.125f; p1[65] = c3s * 0.125f;
            }
        }
    }
}

// ---------------------------------------------------------------------------
// Causal RFA scan, d-split x2, FOUR timesteps per iteration.
// block bx = bh*2 + dh handles output dims d in [dh*32, dh*32+32).
// 256 threads: dl = tid&31, kg = tid>>5. Thread owns s[kg*16+j][dh*32+dl].
// R6-proven 2-sync skeleton, amortized over 4 steps. attn -> bf16 hi/lo.
// ---------------------------------------------------------------------------
__global__ void __launch_bounds__(256) rfa_scan(
    const float* __restrict__ phiq, const float* __restrict__ phik,
    const float* __restrict__ v, __nv_bfloat16* __restrict__ attn_hi,
    __nv_bfloat16* __restrict__ attn_lo)
{
    const int bx = blockIdx.x;       // bh*2 + dh
    const int dh = bx & 1;
    const int bh = bx >> 1;
    const int h = bh & 15;
    const int b = bh >> 4;
    const int tid = threadIdx.x;
    const int dl = tid & 31;
    const int kg = tid >> 5;         // 0..7

    __shared__ float s_pq[2][4][128], s_pk[2][4][128], s_v[2][4][32];
    __shared__ float s_z[128];
    __shared__ float s_red[4][256];   // [step][tid]
    __shared__ float s_qzp[4][4];     // [step][warp128]

    float s_loc[16];
#pragma unroll
    for (int j = 0; j < 16; j++) s_loc[j] = 0.f;
    if (tid < 128) s_z[tid] = 0.f;

    const size_t phi_stride = (size_t)B_DIM * 2048;
    const size_t v_stride   = (size_t)B_DIM * 1024;
    const float* pq_base = phiq + (size_t)b * 2048 + h * 128;
    const float* pk_base = phik + (size_t)b * 2048 + h * 128;
    const float* v_base  = v    + (size_t)b * 1024 + h * 64 + dh * 32;
    const size_t o_off   = (size_t)b * 1024 + h * 64 + dh * 32;

    // preload quad 0 (t = 0..3)
    float ld_pq[4], ld_pk[4], ld_v[4];
#pragma unroll
    for (int s = 0; s < 4; s++) { ld_pq[s] = 0.f; ld_pk[s] = 0.f; ld_v[s] = 0.f; }
    if (tid < 128) {
#pragma unroll
        for (int s = 0; s < 4; s++) {
            ld_pq[s] = pq_base[(size_t)s * phi_stride + tid];
            ld_pk[s] = pk_base[(size_t)s * phi_stride + tid];
        }
    }
    if (tid < 32) {
#pragma unroll
        for (int s = 0; s < 4; s++) ld_v[s] = v_base[(size_t)s * v_stride + tid];
    }
    int buf = 0;
    if (tid < 128) {
#pragma unroll
        for (int s = 0; s < 4; s++) {
            s_pq[0][s][tid] = ld_pq[s];
            s_pk[0][s][tid] = ld_pk[s];
        }
    }
    if (tid < 32) {
#pragma unroll
        for (int s = 0; s < 4; s++) s_v[0][s][tid] = ld_v[s];
    }
    __syncthreads();

    const int NQUAD = T_DIM / 4;   // 512
    for (int it = 0; it < NQUAD; it++) {
        const size_t t0 = (size_t)(4 * it);

        // prefetch quad it+1 (gmem -> regs)
        if (it + 1 < NQUAD) {
            if (tid < 128) {
#pragma unroll
                for (int s = 0; s < 4; s++) {
                    ld_pq[s] = pq_base[(t0 + 4 + s) * phi_stride + tid];
                    ld_pk[s] = pk_base[(t0 + 4 + s) * phi_stride + tid];
                }
            }
            if (tid < 32) {
#pragma unroll
                for (int s = 0; s < 4; s++)
                    ld_v[s] = v_base[(t0 + 4 + s) * v_stride + tid];
            }
        }

        // s updates + q.s partials for 4 steps (sequential in s, interleaved)
        {
            float vd[4];
            const float *pkp[4], *pqp[4];
#pragma unroll
            for (int s = 0; s < 4; s++) {
                vd[s] = s_v[buf][s][dl];
                pkp[s] = &s_pk[buf][s][kg * 16];
                pqp[s] = &s_pq[buf][s][kg * 16];
            }
            float acc[4][4];
#pragma unroll
            for (int s = 0; s < 4; s++)
#pragma unroll
                for (int c = 0; c < 4; c++) acc[s][c] = 0.f;
#pragma unroll
            for (int j = 0; j < 16; j += 4) {
#pragma unroll
                for (int s = 0; s < 4; s++) {
                    float4 kk = *(const float4*)(pkp[s] + j);
                    float4 qq = *(const float4*)(pqp[s] + j);
                    s_loc[j + 0] += kk.x * vd[s]; acc[s][0] += qq.x * s_loc[j + 0];
                    s_loc[j + 1] += kk.y * vd[s]; acc[s][1] += qq.y * s_loc[j + 1];
                    s_loc[j + 2] += kk.z * vd[s]; acc[s][2] += qq.z * s_loc[j + 2];
                    s_loc[j + 3] += kk.w * vd[s]; acc[s][3] += qq.w * s_loc[j + 3];
                }
            }
#pragma unroll
            for (int s = 0; s < 4; s++)
                s_red[s][tid] = (acc[s][0] + acc[s][1]) + (acc[s][2] + acc[s][3]);
        }

        // z updates + qz partials for 4 steps (threads 0..127, one per k)
        {
            float qzp[4] = {0.f, 0.f, 0.f, 0.f};
            if (tid < 128) {
                float z = s_z[tid];
#pragma unroll
                for (int s = 0; s < 4; s++) {
                    z += s_pk[buf][s][tid];
                    qzp[s] = s_pq[buf][s][tid] * z;
                }
                s_z[tid] = z;
            }
#pragma unroll
            for (int off = 16; off; off >>= 1) {
#pragma unroll
                for (int s = 0; s < 4; s++)
                    qzp[s] += __shfl_xor_sync(0xffffffffu, qzp[s], off);
            }
            if (tid < 128 && (tid & 31) == 0) {
#pragma unroll
                for (int s = 0; s < 4; s++) s_qzp[s][tid >> 5] = qzp[s];
            }
        }
        __syncthreads();

        // finalize + write attn[t0..t0+3] for this block's 32 d's
        if (tid < 32) {
#pragma unroll
            for (int stp = 0; stp < 4; stp++) {
                const float* rd = s_red[stp];
                float qs = ((rd[dl] + rd[32 + dl]) + (rd[64 + dl] + rd[96 + dl])) +
                           ((rd[128 + dl] + rd[160 + dl]) + (rd[192 + dl] + rd[224 + dl]));
                float qz = (s_qzp[stp][0] + s_qzp[stp][1]) +
                           (s_qzp[stp][2] + s_qzp[stp][3]);
                qz = fmaxf(qz, EPS_RFA);
                float o = qs / qz;
                __nv_bfloat16 hv = __float2bfloat16(o);
                size_t idx = (t0 + stp) * v_stride + o_off + dl;
                attn_hi[idx] = hv;
                attn_lo[idx] = __float2bfloat16(o - __bfloat162float(hv));
            }
        }

        // stage prefetched quad into the other buffer
        buf ^= 1;
        if (it + 1 < NQUAD) {
            if (tid < 128) {
#pragma unroll
                for (int s = 0; s < 4; s++) {
                    s_pq[buf][s][tid] = ld_pq[s];
                    s_pk[buf][s][tid] = ld_pk[s];
                }
            }
            if (tid < 32) {
#pragma unroll
                for (int s = 0; s < 4; s++) s_v[buf][s][tid] = ld_v[s];
            }
        }
        __syncthreads();
    }
}

// ---------------------------------------------------------------------------
extern "C" void kernel_launch(void* const* d_in, const int* in_sizes, int n_in,
                              void* d_out, int out_size)
{
    const float* x  = (const float*)d_in[0];
    const float* rm = (const float*)d_in[1];
    const float* Wq = (const float*)d_in[2];
    const float* bq = (const float*)d_in[3];
    const float* Wk = (const float*)d_in[4];
    const float* bk = (const float*)d_in[5];
    const float* Wv = (const float*)d_in[6];
    const float* bv = (const float*)d_in[7];
    const float* Wo = (const float*)d_in[8];
    const float* bo = (const float*)d_in[9];
    float* out = (float*)d_out;

    __half *x_hi, *x_lo, *Wq_hi, *Wq_lo, *Wk_hi, *Wk_lo, *Wv_hi, *Wv_lo;
    __nv_bfloat16 *Wo_hi, *Wo_lo, *attn_hi, *attn_lo;
    float *bq_eff, *bk_eff, *vbuf, *phiq, *phik;
    cudaGetSymbolAddress((void**)&x_hi, g_x_hi);
    cudaGetSymbolAddress((void**)&x_lo, g_x_lo);
    cudaGetSymbolAddress((void**)&Wq_hi, g_Wq_hi);
    cudaGetSymbolAddress((void**)&Wq_lo, g_Wq_lo);
    cudaGetSymbolAddress((void**)&Wk_hi, g_Wk_hi);
    cudaGetSymbolAddress((void**)&Wk_lo, g_Wk_lo);
    cudaGetSymbolAddress((void**)&Wv_hi, g_Wv_hi);
    cudaGetSymbolAddress((void**)&Wv_lo, g_Wv_lo);
    cudaGetSymbolAddress((void**)&Wo_hi, g_Wo_hi);
    cudaGetSymbolAddress((void**)&Wo_lo, g_Wo_lo);
    cudaGetSymbolAddress((void**)&attn_hi, g_attn_hi);
    cudaGetSymbolAddress((void**)&attn_lo, g_attn_lo);
    cudaGetSymbolAddress((void**)&bq_eff, g_bq_eff);
    cudaGetSymbolAddress((void**)&bk_eff, g_bk_eff);
    cudaGetSymbolAddress((void**)&vbuf, g_v);
    cudaGetSymbolAddress((void**)&phiq, g_phiq);
    cudaGetSymbolAddress((void**)&phik, g_phik);

    cudaFuncSetAttribute((const void*)tc_gemm<0, __half>,
                         cudaFuncAttributeMaxDynamicSharedMemorySize, SM_TOTAL);
    cudaFuncSetAttribute((const void*)tc_gemm<1, __half>,
                         cudaFuncAttributeMaxDynamicSharedMemorySize, SM_TOTAL);
    cudaFuncSetAttribute((const void*)tc_gemm<0, __nv_bfloat16>,
                         cudaFuncAttributeMaxDynamicSharedMemorySize, SM_TOTAL);

    // conversions + weight prep: x scaled x256 (fp16 lo stays normal),
    // fp16 weights x64; bf16 Wo unscaled.
    f32_to_f16hl<<<TB * E_DIM / 1024, 256>>>(x, x_hi, x_lo, TB * E_DIM, 256.0f);
    prep_weff<<<dim3(16, 16), 256>>>(rm, Wq, bq, Wq_hi, Wq_lo, bq_eff, 0.125f);
    prep_weff<<<dim3(16, 16), 256>>>(rm, Wk, bk, Wk_hi, Wk_lo, bk_eff, 1.0f);
    f32_to_f16hl<<<E_DIM * E_DIM / 1024, 256>>>(Wv, Wv_hi, Wv_lo, E_DIM * E_DIM, 64.0f);
    f32_to_bf16hl<<<E_DIM * E_DIM / 1024, 256>>>(Wo, Wo_hi, Wo_lo, E_DIM * E_DIM);

    // tensor-core GEMMs (escale undoes x256 * x64)
    dim3 gg(E_DIM / BN, TB / BM);   // (8, 128)
    const float inv = 1.0f / 16384.0f;
    tc_gemm<1, __half><<<gg, 256, SM_TOTAL>>>(x_hi, x_lo, Wq_hi, Wq_lo, bq_eff, phiq, inv);
    tc_gemm<1, __half><<<gg, 256, SM_TOTAL>>>(x_hi, x_lo, Wk_hi, Wk_lo, bk_eff, phik, inv);
    tc_gemm<0, __half><<<gg, 256, SM_TOTAL>>>(x_hi, x_lo, Wv_hi, Wv_lo, bv, vbuf, inv);

    // causal scan, d-split x2, 4 timesteps/iter (256 blocks; attn bf16 split)
    rfa_scan<<<B_DIM * H_DIM * 2, 256>>>(phiq, phik, vbuf, attn_hi, attn_lo);

    // output projection (bf16 split, unamplified error path)
    tc_gemm<0, __nv_bfloat16><<<gg, 256, SM_TOTAL>>>(attn_hi, attn_lo, Wo_hi, Wo_lo, bo, out, 1.0f);
}